// round 2
// baseline (speedup 1.0000x reference)
#include <cuda_runtime.h>
#include <math.h>

#define LN_EPS 1e-7f

__device__ float g_XGf[(size_t)16384 * 2048];
__device__ float g_XGb[(size_t)16384 * 2048];
__device__ float g_ENC[(size_t)16 * 1024 * 1024];
__device__ float g_FEATP[512 * 1024];
__device__ float g_FEAT [512 * 1024];
__device__ float g_Qm[512 * 1024];
__device__ float g_Km[512 * 1024];
__device__ float g_Vm[512 * 1024];
__device__ float g_CTX[512 * 1024];
__device__ float g_TMP[512 * 1024];
__device__ float g_ATT[512 * 1024];
__device__ unsigned g_bar_arrive;
__device__ unsigned g_bar_epoch;

// ---------------- C[M,N] = A[M,K] * B[N,K]^T + bias[N] ----------------
__global__ __launch_bounds__(256) void sgemm_tn(
    const float* __restrict__ A, const float* __restrict__ B,
    const float* __restrict__ bias, float* __restrict__ C,
    int M, int N, int K)
{
    __shared__ __align__(16) float As[8][128];
    __shared__ __align__(16) float Bs[8][128];
    const int tid  = threadIdx.x;
    const int brow = blockIdx.y * 128;
    const int bcol = blockIdx.x * 128;
    const int lr = tid >> 1;
    const int lk = (tid & 1) * 4;
    const float* Aptr = A + (size_t)(brow + lr) * K + lk;
    const float* Bptr = B + (size_t)(bcol + lr) * K + lk;
    const int tx = tid & 15;
    const int ty = tid >> 4;

    float acc[8][8];
#pragma unroll
    for (int i = 0; i < 8; ++i)
#pragma unroll
        for (int j = 0; j < 8; ++j) acc[i][j] = 0.f;

    float4 aR = *(const float4*)Aptr;
    float4 bR = *(const float4*)Bptr;

    for (int kt = 0; kt < K; kt += 8) {
        As[lk+0][lr] = aR.x; As[lk+1][lr] = aR.y; As[lk+2][lr] = aR.z; As[lk+3][lr] = aR.w;
        Bs[lk+0][lr] = bR.x; Bs[lk+1][lr] = bR.y; Bs[lk+2][lr] = bR.z; Bs[lk+3][lr] = bR.w;
        __syncthreads();
        if (kt + 8 < K) {
            aR = *(const float4*)(Aptr + kt + 8);
            bR = *(const float4*)(Bptr + kt + 8);
        }
#pragma unroll
        for (int kk = 0; kk < 8; ++kk) {
            float a[8], b[8];
            *(float4*)(a)   = *(const float4*)&As[kk][ty*8];
            *(float4*)(a+4) = *(const float4*)&As[kk][ty*8+4];
            *(float4*)(b)   = *(const float4*)&Bs[kk][tx*8];
            *(float4*)(b+4) = *(const float4*)&Bs[kk][tx*8+4];
#pragma unroll
            for (int i = 0; i < 8; ++i)
#pragma unroll
                for (int j = 0; j < 8; ++j)
                    acc[i][j] += a[i] * b[j];
        }
        __syncthreads();
    }

    float bb[8];
#pragma unroll
    for (int j = 0; j < 8; ++j) bb[j] = bias[bcol + tx*8 + j];
#pragma unroll
    for (int i = 0; i < 8; ++i) {
        float* crow = C + (size_t)(brow + ty*8 + i) * N + bcol + tx*8;
#pragma unroll
        for (int j = 0; j < 8; ++j) crow[j] = acc[i][j] + bb[j];
    }
}

// ---------------- persistent bi-LSTM recurrence ----------------
__device__ __forceinline__ float sigmoidf_(float x) { return 1.f / (1.f + expf(-x)); }

__global__ __launch_bounds__(256) void lstm_rec(
    const float* __restrict__ whh_f, const float* __restrict__ whh_b)
{
    extern __shared__ float sm[];
    float* ws   = sm;                 // [32][513] recurrent weights slice
    float* ubuf = ws + 32 * 513;      // 8704: hs[512][17] OR red[16][512]
    float* Gs   = ubuf + 8704;        // [512]
    float* cst  = Gs + 512;           // [128]
    __shared__ unsigned s_base;

    const int tid = threadIdx.x;
    const int dir = blockIdx.x & 1;
    const int grp = blockIdx.x >> 1;
    const float* whh = dir ? whh_b : whh_f;
    const float* xg  = dir ? g_XGb : g_XGf;

    for (int idx = tid; idx < 32 * 512; idx += 256) {
        int c = idx >> 9, k = idx & 511;
        int j = (c >> 3) * 512 + grp * 8 + (c & 7);
        ws[c * 513 + k] = whh[(size_t)j * 512 + k];
    }
    if (tid < 128) cst[tid] = 0.f;
    if (tid == 0) s_base = atomicAdd(&g_bar_epoch, 0u);
    __syncthreads();
    const unsigned base = s_base;

    const int ks = tid >> 4;
    const int b4 = ((tid >> 2) & 3) * 4;
    const int c8 = (tid & 3) * 8;
    const int kb = ks * 32;
    const int stag = (ks & 1) * 4;

    for (int s = 0; s < 1024; ++s) {
        const int tcur = dir ? (1023 - s) : s;
        if (s == 0) {
            for (int idx = tid; idx < 8704; idx += 256) ubuf[idx] = 0.f;
        } else {
            const int tprev = dir ? (tcur + 1) : (tcur - 1);
            const int b  = tid >> 4;
            const int k0 = (tid & 15) * 32;
            const float* src = g_ENC + ((size_t)b * 1024 + tprev) * 1024 + dir * 512 + k0;
#pragma unroll
            for (int j = 0; j < 32; j += 4) {
                float4 v = *(const float4*)(src + j);
                ubuf[(k0+j+0)*17 + b] = v.x; ubuf[(k0+j+1)*17 + b] = v.y;
                ubuf[(k0+j+2)*17 + b] = v.z; ubuf[(k0+j+3)*17 + b] = v.w;
            }
        }
        __syncthreads();

        float acc[4][8];
#pragma unroll
        for (int i = 0; i < 4; ++i)
#pragma unroll
            for (int j = 0; j < 8; ++j) acc[i][j] = 0.f;
#pragma unroll 8
        for (int kk = 0; kk < 32; ++kk) {
            const int k = kb + ((kk + stag) & 31);
            const float h0 = ubuf[k*17 + b4+0];
            const float h1 = ubuf[k*17 + b4+1];
            const float h2 = ubuf[k*17 + b4+2];
            const float h3 = ubuf[k*17 + b4+3];
#pragma unroll
            for (int j = 0; j < 8; ++j) {
                const float w = ws[(c8+j)*513 + k];
                acc[0][j] += h0*w; acc[1][j] += h1*w;
                acc[2][j] += h2*w; acc[3][j] += h3*w;
            }
        }
        __syncthreads();
#pragma unroll
        for (int i = 0; i < 4; ++i)
#pragma unroll
            for (int j = 0; j < 8; ++j)
                ubuf[ks*512 + (b4+i)*32 + c8 + j] = acc[i][j];
        __syncthreads();

#pragma unroll
        for (int rep = 0; rep < 2; ++rep) {
            const int o = tid + rep * 256;
            float sum = 0.f;
#pragma unroll
            for (int kq = 0; kq < 16; ++kq) sum += ubuf[kq*512 + o];
            Gs[o] = sum;
        }
        __syncthreads();

        if (tid < 128) {
            const int b = tid >> 3, u = tid & 7;
            const size_t xbase = ((size_t)b * 1024 + tcur) * 2048 + grp * 8 + u;
            const float gi = Gs[b*32 +  0 + u] + xg[xbase       ];
            const float gf = Gs[b*32 +  8 + u] + xg[xbase +  512];
            const float gg = Gs[b*32 + 16 + u] + xg[xbase + 1024];
            const float go = Gs[b*32 + 24 + u] + xg[xbase + 1536];
            const float cn = sigmoidf_(gf) * cst[tid] + sigmoidf_(gi) * tanhf(gg);
            cst[tid] = cn;
            g_ENC[((size_t)b*1024 + tcur)*1024 + dir*512 + grp*8 + u] = sigmoidf_(go) * tanhf(cn);
        }
        __syncthreads();
        if (tid == 0) {
            __threadfence();
            unsigned a = atomicAdd(&g_bar_arrive, 1u);
            if (a == gridDim.x - 1) {
                atomicExch(&g_bar_arrive, 0u);
                __threadfence();
                atomicAdd(&g_bar_epoch, 1u);
            } else {
                while (atomicAdd(&g_bar_epoch, 0u) - base < (unsigned)(s + 1)) { }
            }
        }
        __syncthreads();
    }
}

// ---------------- span mean pooling ----------------
__global__ __launch_bounds__(256) void pool_kernel(
    const int* __restrict__ heads, const int* __restrict__ tails)
{
    const int bs = blockIdx.x;
    const int b = bs >> 5;
    int lo = heads[bs] + 1, hi = tails[bs];
    if (lo < 0) lo = 0;
    if (hi > 1024) hi = 1024;
    int cnt = hi - lo; if (cnt < 1) cnt = 1;
    const float inv = 1.f / (float)cnt;
    const int h0 = threadIdx.x * 4;
    float ax = 0.f, ay = 0.f, az = 0.f, aw = 0.f;
    for (int t = lo; t < hi; ++t) {
        const float4 v = *(const float4*)(g_ENC + ((size_t)b*1024 + t)*1024 + h0);
        ax += v.x; ay += v.y; az += v.z; aw += v.w;
    }
    float4 o; o.x = ax*inv; o.y = ay*inv; o.z = az*inv; o.w = aw*inv;
    *(float4*)(g_FEATP + (size_t)bs*1024 + h0) = o;
}

// ---------------- row LayerNorm (optional residual) ----------------
__global__ __launch_bounds__(256) void ln_kernel(
    const float* __restrict__ X, const float* __restrict__ R,
    const float* __restrict__ gam, const float* __restrict__ bet,
    float* __restrict__ Y)
{
    const int r = blockIdx.x;
    const int tid = threadIdx.x;
    const size_t off = (size_t)r * 1024 + tid * 4;
    float4 v = *(const float4*)(X + off);
    if (R) {
        const float4 rv = *(const float4*)(R + off);
        v.x += rv.x; v.y += rv.y; v.z += rv.z; v.w += rv.w;
    }
    float s  = v.x + v.y + v.z + v.w;
    float ss = v.x*v.x + v.y*v.y + v.z*v.z + v.w*v.w;
#pragma unroll
    for (int o = 16; o; o >>= 1) {
        s  += __shfl_xor_sync(0xffffffffu, s, o);
        ss += __shfl_xor_sync(0xffffffffu, ss, o);
    }
    __shared__ float as_[8], ass_[8];
    if ((tid & 31) == 0) { as_[tid>>5] = s; ass_[tid>>5] = ss; }
    __syncthreads();
    s = 0.f; ss = 0.f;
#pragma unroll
    for (int w = 0; w < 8; ++w) { s += as_[w]; ss += ass_[w]; }
    const float mu  = s * (1.f/1024.f);
    const float var = ss * (1.f/1024.f) - mu*mu;
    const float inv = rsqrtf(var + LN_EPS);
    const int c0 = tid * 4;
    float4 o;
    o.x = (v.x-mu)*inv*gam[c0+0] + bet[c0+0];
    o.y = (v.y-mu)*inv*gam[c0+1] + bet[c0+1];
    o.z = (v.z-mu)*inv*gam[c0+2] + bet[c0+2];
    o.w = (v.w-mu)*inv*gam[c0+3] + bet[c0+3];
    *(float4*)(Y + off) = o;
}

// ---------------- span attention: one CTA per (batch, head) ----------------
__global__ __launch_bounds__(256) void attn_kernel(const int* __restrict__ amask)
{
    const int bh = blockIdx.x;
    const int b = bh >> 4, h = bh & 15;
    __shared__ float qs[2048], ksm[2048], vsm[2048], sc[32*33];
    __shared__ int ms[32];
    const int tid = threadIdx.x;
    for (int idx = tid; idx < 2048; idx += 256) {
        const int s = idx >> 6, d = idx & 63;
        const size_t off = (size_t)(b*32 + s)*1024 + h*64 + d;
        qs[idx] = g_Qm[off]; ksm[idx] = g_Km[off]; vsm[idx] = g_Vm[off];
    }
    if (tid < 32) ms[tid] = amask[b*32 + tid];
    __syncthreads();
    for (int idx = tid; idx < 1024; idx += 256) {
        const int i = idx >> 5, j = idx & 31;
        float d0 = 0.f;
#pragma unroll
        for (int k = 0; k < 64; ++k) d0 += qs[i*64+k] * ksm[j*64+k];
        sc[i*33 + j] = d0 * 0.125f;
    }
    __syncthreads();
    const int w = tid >> 5, l = tid & 31;
    for (int i = w; i < 32; i += 8) {
        const bool valid = (ms[i] != 0) && (ms[l] != 0);
        float v = valid ? sc[i*33 + l] : -3.402823466e38f;
        float mx = v;
#pragma unroll
        for (int o = 16; o; o >>= 1) mx = fmaxf(mx, __shfl_xor_sync(0xffffffffu, mx, o));
        float e = expf(v - mx);
        float sum = e;
#pragma unroll
        for (int o = 16; o; o >>= 1) sum += __shfl_xor_sync(0xffffffffu, sum, o);
        float p = e / sum;
        if (!valid) p = 0.f;
        sc[i*33 + l] = p;
    }
    __syncthreads();
    for (int idx = tid; idx < 2048; idx += 256) {
        const int s = idx >> 6, d = idx & 63;
        float a = 0.f;
#pragma unroll
        for (int j = 0; j < 32; ++j) a += sc[s*33 + j] * vsm[j*64 + d];
        g_CTX[(size_t)(b*32 + s)*1024 + h*64 + d] = a;
    }
}

// ---------------- classifier ----------------
__global__ __launch_bounds__(96) void cls_kernel(
    const float* __restrict__ wc, const float* __restrict__ bc,
    float* __restrict__ out)
{
    const int r = blockIdx.x;
    const int lbl = threadIdx.x >> 5, lane = threadIdx.x & 31;
    const float* a = g_ATT + (size_t)r * 1024 + lane * 32;
    const float* w = wc + (size_t)lbl * 1024 + lane * 32;
    float s = 0.f;
#pragma unroll
    for (int k = 0; k < 32; ++k) s += a[k] * w[k];
#pragma unroll
    for (int o = 16; o; o >>= 1) s += __shfl_xor_sync(0xffffffffu, s, o);
    if (lane == 0) out[r * 3 + lbl] = s + bc[lbl];
}

extern "C" void kernel_launch(void* const* d_in, const int* in_sizes, int n_in,
                              void* d_out, int out_size) {
    const float* hs    = (const float*)d_in[0];
    const float* wih_f = (const float*)d_in[1];
    const float* whh_f = (const float*)d_in[2];
    const float* b_f   = (const float*)d_in[3];
    const float* wih_b = (const float*)d_in[4];
    const float* whh_b = (const float*)d_in[5];
    const float* b_b   = (const float*)d_in[6];
    const float* ln_g  = (const float*)d_in[7];
    const float* ln_b  = (const float*)d_in[8];
    const float* wq = (const float*)d_in[9];  const float* bq = (const float*)d_in[10];
    const float* wk = (const float*)d_in[11]; const float* bk = (const float*)d_in[12];
    const float* wv = (const float*)d_in[13]; const float* bv = (const float*)d_in[14];
    const float* wo = (const float*)d_in[15]; const float* bo = (const float*)d_in[16];
    const float* aln_g = (const float*)d_in[17];
    const float* aln_b = (const float*)d_in[18];
    const float* wc = (const float*)d_in[19]; const float* bc = (const float*)d_in[20];
    const int* heads = (const int*)d_in[21];
    const int* tails = (const int*)d_in[22];
    const int* amask = (const int*)d_in[23];
    float* out = (float*)d_out;

    float *XGf, *XGb, *FEATP, *FEAT, *Qm, *Km, *Vm, *CTX, *TMP, *ATT;
    cudaGetSymbolAddress((void**)&XGf, g_XGf);
    cudaGetSymbolAddress((void**)&XGb, g_XGb);
    cudaGetSymbolAddress((void**)&FEATP, g_FEATP);
    cudaGetSymbolAddress((void**)&FEAT, g_FEAT);
    cudaGetSymbolAddress((void**)&Qm, g_Qm);
    cudaGetSymbolAddress((void**)&Km, g_Km);
    cudaGetSymbolAddress((void**)&Vm, g_Vm);
    cudaGetSymbolAddress((void**)&CTX, g_CTX);
    cudaGetSymbolAddress((void**)&TMP, g_TMP);
    cudaGetSymbolAddress((void**)&ATT, g_ATT);

    // input-gate GEMMs: [16384,1024] x [2048,1024]^T
    dim3 gXG(2048/128, 16384/128);
    sgemm_tn<<<gXG, 256>>>(hs, wih_f, b_f, XGf, 16384, 2048, 1024);
    sgemm_tn<<<gXG, 256>>>(hs, wih_b, b_b, XGb, 16384, 2048, 1024);

    // persistent recurrence
    const int smem = (32*513 + 8704 + 512 + 128) * 4;
    cudaFuncSetAttribute(lstm_rec, cudaFuncAttributeMaxDynamicSharedMemorySize, smem);
    lstm_rec<<<128, 256, smem>>>(whh_f, whh_b);

    pool_kernel<<<512, 256>>>(heads, tails);
    ln_kernel<<<512, 256>>>(FEATP, nullptr, ln_g, ln_b, FEAT);

    dim3 gP(1024/128, 512/128);
    sgemm_tn<<<gP, 256>>>(FEAT, wq, bq, Qm, 512, 1024, 1024);
    sgemm_tn<<<gP, 256>>>(FEAT, wk, bk, Km, 512, 1024, 1024);
    sgemm_tn<<<gP, 256>>>(FEAT, wv, bv, Vm, 512, 1024, 1024);

    attn_kernel<<<256, 256>>>(amask);

    sgemm_tn<<<gP, 256>>>(CTX, wo, bo, TMP, 512, 1024, 1024);
    ln_kernel<<<512, 256>>>(TMP, FEAT, aln_g, aln_b, ATT);

    cls_kernel<<<512, 96>>>(wc, bc, out);
}

// round 3
// speedup vs baseline: 1.0871x; 1.0871x over previous
#include <cuda_runtime.h>
#include <mma.h>
#include <math.h>

using namespace nvcuda;

#define LN_EPS 1e-7f

__device__ float g_XGf[(size_t)16384 * 2048];
__device__ float g_XGb[(size_t)16384 * 2048];
__device__ float g_ENC[(size_t)16 * 1024 * 1024];
__device__ float g_FEATP[512 * 1024];
__device__ float g_FEAT [512 * 1024];
__device__ float g_Qm[512 * 1024];
__device__ float g_Km[512 * 1024];
__device__ float g_Vm[512 * 1024];
__device__ float g_CTX[512 * 1024];
__device__ float g_TMP[512 * 1024];
__device__ float g_ATT[512 * 1024];
__device__ unsigned g_bar_arrive;
__device__ unsigned g_bar_epoch;

// =====================================================================
// TF32 tensor-core GEMM: C[M,N] = A[M,K] * B[N,K]^T + bias[N]
// CTA tile 128x128, BK=32, 256 threads (8 warps as 4m x 2n, warp tile 32x64).
// Requires M%128==0, N%128==0, K%32==0.
// dynamic smem: stage As[128][36]+Bs[128][36] (36KB) aliased with Co[128][132] (67.5KB)
// =====================================================================
#define LDT 36
#define LDC 132

__global__ __launch_bounds__(256) void gemm_tf32(
    const float* __restrict__ A, const float* __restrict__ B,
    const float* __restrict__ bias, float* __restrict__ C,
    int M, int N, int K)
{
    extern __shared__ float smem[];
    float* As = smem;
    float* Bs = smem + 128 * LDT;
    float* Co = smem;

    const int tid = threadIdx.x;
    const int wid = tid >> 5;
    const int brow = blockIdx.y * 128;
    const int bcol = blockIdx.x * 128;
    const int wm = (wid & 3) * 32;
    const int wn = (wid >> 2) * 64;

    wmma::fragment<wmma::accumulator, 16, 16, 8, float> acc[2][4];
#pragma unroll
    for (int i = 0; i < 2; ++i)
#pragma unroll
        for (int j = 0; j < 4; ++j) wmma::fill_fragment(acc[i][j], 0.f);

    const float* Ag = A + (size_t)brow * K;
    const float* Bg = B + (size_t)bcol * K;

    float4 aR[4], bR[4];
#pragma unroll
    for (int p = 0; p < 4; ++p) {
        const int idx = tid + p * 256;
        const int r = idx >> 3, c4 = (idx & 7) * 4;
        aR[p] = *(const float4*)(Ag + (size_t)r * K + c4);
        bR[p] = *(const float4*)(Bg + (size_t)r * K + c4);
    }

    for (int kt = 0; kt < K; kt += 32) {
#pragma unroll
        for (int p = 0; p < 4; ++p) {
            const int idx = tid + p * 256;
            const int r = idx >> 3, c4 = (idx & 7) * 4;
            *(float4*)(As + r * LDT + c4) = aR[p];
            *(float4*)(Bs + r * LDT + c4) = bR[p];
        }
        __syncthreads();
        if (kt + 32 < K) {
#pragma unroll
            for (int p = 0; p < 4; ++p) {
                const int idx = tid + p * 256;
                const int r = idx >> 3, c4 = (idx & 7) * 4;
                aR[p] = *(const float4*)(Ag + (size_t)r * K + kt + 32 + c4);
                bR[p] = *(const float4*)(Bg + (size_t)r * K + kt + 32 + c4);
            }
        }
#pragma unroll
        for (int kk = 0; kk < 32; kk += 8) {
            wmma::fragment<wmma::matrix_a, 16, 16, 8, wmma::precision::tf32, wmma::row_major> af[2];
            wmma::fragment<wmma::matrix_b, 16, 16, 8, wmma::precision::tf32, wmma::col_major> bf[4];
#pragma unroll
            for (int i = 0; i < 2; ++i) {
                wmma::load_matrix_sync(af[i], As + (wm + i * 16) * LDT + kk, LDT);
#pragma unroll
                for (int t = 0; t < af[i].num_elements; ++t)
                    af[i].x[t] = wmma::__float_to_tf32(af[i].x[t]);
            }
#pragma unroll
            for (int j = 0; j < 4; ++j) {
                wmma::load_matrix_sync(bf[j], Bs + (wn + j * 16) * LDT + kk, LDT);
#pragma unroll
                for (int t = 0; t < bf[j].num_elements; ++t)
                    bf[j].x[t] = wmma::__float_to_tf32(bf[j].x[t]);
            }
#pragma unroll
            for (int i = 0; i < 2; ++i)
#pragma unroll
                for (int j = 0; j < 4; ++j)
                    wmma::mma_sync(acc[i][j], af[i], bf[j], acc[i][j]);
        }
        __syncthreads();
    }

#pragma unroll
    for (int i = 0; i < 2; ++i)
#pragma unroll
        for (int j = 0; j < 4; ++j)
            wmma::store_matrix_sync(Co + (wm + i * 16) * LDC + wn + j * 16,
                                    acc[i][j], LDC, wmma::mem_row_major);
    __syncthreads();

    for (int idx = tid; idx < 128 * 32; idx += 256) {
        const int r = idx >> 5, c4 = (idx & 31) * 4;
        float4 v = *(float4*)(Co + r * LDC + c4);
        v.x += bias[bcol + c4 + 0];
        v.y += bias[bcol + c4 + 1];
        v.z += bias[bcol + c4 + 2];
        v.w += bias[bcol + c4 + 3];
        *(float4*)(C + (size_t)(brow + r) * N + bcol + c4) = v;
    }
}

// ---------------- persistent bi-LSTM recurrence ----------------
__device__ __forceinline__ float sigmoidf_(float x) { return 1.f / (1.f + expf(-x)); }

__global__ __launch_bounds__(256) void lstm_rec(
    const float* __restrict__ whh_f, const float* __restrict__ whh_b)
{
    extern __shared__ float sm[];
    float* ws   = sm;                 // [32][513]
    float* ubuf = ws + 32 * 513;      // 8704: hs[512][17] OR red[16][512]
    float* Gs   = ubuf + 8704;        // [512]
    float* cst  = Gs + 512;           // [128]
    __shared__ unsigned s_base;

    const int tid = threadIdx.x;
    const int dir = blockIdx.x & 1;
    const int grp = blockIdx.x >> 1;
    const float* whh = dir ? whh_b : whh_f;
    const float* xg  = dir ? g_XGb : g_XGf;

    for (int idx = tid; idx < 32 * 512; idx += 256) {
        int c = idx >> 9, k = idx & 511;
        int j = (c >> 3) * 512 + grp * 8 + (c & 7);
        ws[c * 513 + k] = whh[(size_t)j * 512 + k];
    }
    if (tid < 128) cst[tid] = 0.f;
    if (tid == 0) s_base = atomicAdd(&g_bar_epoch, 0u);
    __syncthreads();
    const unsigned base = s_base;

    const int ks = tid >> 4;
    const int b4 = ((tid >> 2) & 3) * 4;
    const int c8 = (tid & 3) * 8;
    const int kb = ks * 32;
    const int stag = (ks & 1) * 4;

    for (int s = 0; s < 1024; ++s) {
        const int tcur = dir ? (1023 - s) : s;
        if (s == 0) {
            for (int idx = tid; idx < 8704; idx += 256) ubuf[idx] = 0.f;
        } else {
            const int tprev = dir ? (tcur + 1) : (tcur - 1);
            const int b  = tid >> 4;
            const int k0 = (tid & 15) * 32;
            const float* src = g_ENC + ((size_t)b * 1024 + tprev) * 1024 + dir * 512 + k0;
#pragma unroll
            for (int j = 0; j < 32; j += 4) {
                float4 v = *(const float4*)(src + j);
                ubuf[(k0+j+0)*17 + b] = v.x; ubuf[(k0+j+1)*17 + b] = v.y;
                ubuf[(k0+j+2)*17 + b] = v.z; ubuf[(k0+j+3)*17 + b] = v.w;
            }
        }
        __syncthreads();

        float acc[4][8];
#pragma unroll
        for (int i = 0; i < 4; ++i)
#pragma unroll
            for (int j = 0; j < 8; ++j) acc[i][j] = 0.f;
#pragma unroll 8
        for (int kk = 0; kk < 32; ++kk) {
            const int k = kb + ((kk + stag) & 31);
            const float h0 = ubuf[k*17 + b4+0];
            const float h1 = ubuf[k*17 + b4+1];
            const float h2 = ubuf[k*17 + b4+2];
            const float h3 = ubuf[k*17 + b4+3];
#pragma unroll
            for (int j = 0; j < 8; ++j) {
                const float w = ws[(c8+j)*513 + k];
                acc[0][j] += h0*w; acc[1][j] += h1*w;
                acc[2][j] += h2*w; acc[3][j] += h3*w;
            }
        }
        __syncthreads();
#pragma unroll
        for (int i = 0; i < 4; ++i)
#pragma unroll
            for (int j = 0; j < 8; ++j)
                ubuf[ks*512 + (b4+i)*32 + c8 + j] = acc[i][j];
        __syncthreads();

#pragma unroll
        for (int rep = 0; rep < 2; ++rep) {
            const int o = tid + rep * 256;
            float sum = 0.f;
#pragma unroll
            for (int kq = 0; kq < 16; ++kq) sum += ubuf[kq*512 + o];
            Gs[o] = sum;
        }
        __syncthreads();

        if (tid < 128) {
            const int b = tid >> 3, u = tid & 7;
            const size_t xbase = ((size_t)b * 1024 + tcur) * 2048 + grp * 8 + u;
            const float gi = Gs[b*32 +  0 + u] + xg[xbase       ];
            const float gf = Gs[b*32 +  8 + u] + xg[xbase +  512];
            const float gg = Gs[b*32 + 16 + u] + xg[xbase + 1024];
            const float go = Gs[b*32 + 24 + u] + xg[xbase + 1536];
            const float cn = sigmoidf_(gf) * cst[tid] + sigmoidf_(gi) * tanhf(gg);
            cst[tid] = cn;
            g_ENC[((size_t)b*1024 + tcur)*1024 + dir*512 + grp*8 + u] = sigmoidf_(go) * tanhf(cn);
        }
        __syncthreads();
        if (tid == 0) {
            __threadfence();
            unsigned a = atomicAdd(&g_bar_arrive, 1u);
            if (a == gridDim.x - 1) {
                atomicExch(&g_bar_arrive, 0u);
                __threadfence();
                atomicAdd(&g_bar_epoch, 1u);
            } else {
                volatile unsigned* ep = &g_bar_epoch;
                while (*ep - base < (unsigned)(s + 1)) { }
                __threadfence();
            }
        }
        __syncthreads();
    }
}

// ---------------- span mean pooling ----------------
__global__ __launch_bounds__(256) void pool_kernel(
    const int* __restrict__ heads, const int* __restrict__ tails)
{
    const int bs = blockIdx.x;
    const int b = bs >> 5;
    int lo = heads[bs] + 1, hi = tails[bs];
    if (lo < 0) lo = 0;
    if (hi > 1024) hi = 1024;
    int cnt = hi - lo; if (cnt < 1) cnt = 1;
    const float inv = 1.f / (float)cnt;
    const int h0 = threadIdx.x * 4;
    float ax = 0.f, ay = 0.f, az = 0.f, aw = 0.f;
    for (int t = lo; t < hi; ++t) {
        const float4 v = *(const float4*)(g_ENC + ((size_t)b*1024 + t)*1024 + h0);
        ax += v.x; ay += v.y; az += v.z; aw += v.w;
    }
    float4 o; o.x = ax*inv; o.y = ay*inv; o.z = az*inv; o.w = aw*inv;
    *(float4*)(g_FEATP + (size_t)bs*1024 + h0) = o;
}

// ---------------- row LayerNorm (optional residual) ----------------
__global__ __launch_bounds__(256) void ln_kernel(
    const float* __restrict__ X, const float* __restrict__ R,
    const float* __restrict__ gam, const float* __restrict__ bet,
    float* __restrict__ Y)
{
    const int r = blockIdx.x;
    const int tid = threadIdx.x;
    const size_t off = (size_t)r * 1024 + tid * 4;
    float4 v = *(const float4*)(X + off);
    if (R) {
        const float4 rv = *(const float4*)(R + off);
        v.x += rv.x; v.y += rv.y; v.z += rv.z; v.w += rv.w;
    }
    float s  = v.x + v.y + v.z + v.w;
    float ss = v.x*v.x + v.y*v.y + v.z*v.z + v.w*v.w;
#pragma unroll
    for (int o = 16; o; o >>= 1) {
        s  += __shfl_xor_sync(0xffffffffu, s, o);
        ss += __shfl_xor_sync(0xffffffffu, ss, o);
    }
    __shared__ float as_[8], ass_[8];
    if ((tid & 31) == 0) { as_[tid>>5] = s; ass_[tid>>5] = ss; }
    __syncthreads();
    s = 0.f; ss = 0.f;
#pragma unroll
    for (int w = 0; w < 8; ++w) { s += as_[w]; ss += ass_[w]; }
    const float mu  = s * (1.f/1024.f);
    const float var = ss * (1.f/1024.f) - mu*mu;
    const float inv = rsqrtf(var + LN_EPS);
    const int c0 = tid * 4;
    float4 o;
    o.x = (v.x-mu)*inv*gam[c0+0] + bet[c0+0];
    o.y = (v.y-mu)*inv*gam[c0+1] + bet[c0+1];
    o.z = (v.z-mu)*inv*gam[c0+2] + bet[c0+2];
    o.w = (v.w-mu)*inv*gam[c0+3] + bet[c0+3];
    *(float4*)(Y + off) = o;
}

// ---------------- span attention: one CTA per (batch, head) ----------------
__global__ __launch_bounds__(256) void attn_kernel(const int* __restrict__ amask)
{
    const int bh = blockIdx.x;
    const int b = bh >> 4, h = bh & 15;
    __shared__ float qs[2048], ksm[2048], vsm[2048], sc[32*33];
    __shared__ int ms[32];
    const int tid = threadIdx.x;
    for (int idx = tid; idx < 2048; idx += 256) {
        const int s = idx >> 6, d = idx & 63;
        const size_t off = (size_t)(b*32 + s)*1024 + h*64 + d;
        qs[idx] = g_Qm[off]; ksm[idx] = g_Km[off]; vsm[idx] = g_Vm[off];
    }
    if (tid < 32) ms[tid] = amask[b*32 + tid];
    __syncthreads();
    for (int idx = tid; idx < 1024; idx += 256) {
        const int i = idx >> 5, j = idx & 31;
        float d0 = 0.f;
#pragma unroll
        for (int k = 0; k < 64; ++k) d0 += qs[i*64+k] * ksm[j*64+k];
        sc[i*33 + j] = d0 * 0.125f;
    }
    __syncthreads();
    const int w = tid >> 5, l = tid & 31;
    for (int i = w; i < 32; i += 8) {
        const bool valid = (ms[i] != 0) && (ms[l] != 0);
        float v = valid ? sc[i*33 + l] : -3.402823466e38f;
        float mx = v;
#pragma unroll
        for (int o = 16; o; o >>= 1) mx = fmaxf(mx, __shfl_xor_sync(0xffffffffu, mx, o));
        float e = expf(v - mx);
        float sum = e;
#pragma unroll
        for (int o = 16; o; o >>= 1) sum += __shfl_xor_sync(0xffffffffu, sum, o);
        float p = e / sum;
        if (!valid) p = 0.f;
        sc[i*33 + l] = p;
    }
    __syncthreads();
    for (int idx = tid; idx < 2048; idx += 256) {
        const int s = idx >> 6, d = idx & 63;
        float a = 0.f;
#pragma unroll
        for (int j = 0; j < 32; ++j) a += sc[s*33 + j] * vsm[j*64 + d];
        g_CTX[(size_t)(b*32 + s)*1024 + h*64 + d] = a;
    }
}

// ---------------- classifier ----------------
__global__ __launch_bounds__(96) void cls_kernel(
    const float* __restrict__ wc, const float* __restrict__ bc,
    float* __restrict__ out)
{
    const int r = blockIdx.x;
    const int lbl = threadIdx.x >> 5, lane = threadIdx.x & 31;
    const float* a = g_ATT + (size_t)r * 1024 + lane * 32;
    const float* w = wc + (size_t)lbl * 1024 + lane * 32;
    float s = 0.f;
#pragma unroll
    for (int k = 0; k < 32; ++k) s += a[k] * w[k];
#pragma unroll
    for (int o = 16; o; o >>= 1) s += __shfl_xor_sync(0xffffffffu, s, o);
    if (lane == 0) out[r * 3 + lbl] = s + bc[lbl];
}

extern "C" void kernel_launch(void* const* d_in, const int* in_sizes, int n_in,
                              void* d_out, int out_size) {
    const float* hs    = (const float*)d_in[0];
    const float* wih_f = (const float*)d_in[1];
    const float* whh_f = (const float*)d_in[2];
    const float* b_f   = (const float*)d_in[3];
    const float* wih_b = (const float*)d_in[4];
    const float* whh_b = (const float*)d_in[5];
    const float* b_b   = (const float*)d_in[6];
    const float* ln_g  = (const float*)d_in[7];
    const float* ln_b  = (const float*)d_in[8];
    const float* wq = (const float*)d_in[9];  const float* bq = (const float*)d_in[10];
    const float* wk = (const float*)d_in[11]; const float* bk = (const float*)d_in[12];
    const float* wv = (const float*)d_in[13]; const float* bv = (const float*)d_in[14];
    const float* wo = (const float*)d_in[15]; const float* bo = (const float*)d_in[16];
    const float* aln_g = (const float*)d_in[17];
    const float* aln_b = (const float*)d_in[18];
    const float* wc = (const float*)d_in[19]; const float* bc = (const float*)d_in[20];
    const int* heads = (const int*)d_in[21];
    const int* tails = (const int*)d_in[22];
    const int* amask = (const int*)d_in[23];
    float* out = (float*)d_out;

    float *XGf, *XGb, *FEATP, *FEAT, *Qm, *Km, *Vm, *CTX, *TMP, *ATT;
    cudaGetSymbolAddress((void**)&XGf, g_XGf);
    cudaGetSymbolAddress((void**)&XGb, g_XGb);
    cudaGetSymbolAddress((void**)&FEATP, g_FEATP);
    cudaGetSymbolAddress((void**)&FEAT, g_FEAT);
    cudaGetSymbolAddress((void**)&Qm, g_Qm);
    cudaGetSymbolAddress((void**)&Km, g_Km);
    cudaGetSymbolAddress((void**)&Vm, g_Vm);
    cudaGetSymbolAddress((void**)&CTX, g_CTX);
    cudaGetSymbolAddress((void**)&TMP, g_TMP);
    cudaGetSymbolAddress((void**)&ATT, g_ATT);

    const int gemm_smem = 128 * LDC * sizeof(float);  // 67584
    cudaFuncSetAttribute(gemm_tf32, cudaFuncAttributeMaxDynamicSharedMemorySize, gemm_smem);

    // input-gate GEMMs: [16384,1024] x [2048,1024]^T
    dim3 gXG(2048/128, 16384/128);
    gemm_tf32<<<gXG, 256, gemm_smem>>>(hs, wih_f, b_f, XGf, 16384, 2048, 1024);
    gemm_tf32<<<gXG, 256, gemm_smem>>>(hs, wih_b, b_b, XGb, 16384, 2048, 1024);

    // persistent recurrence
    const int smem = (32*513 + 8704 + 512 + 128) * 4;
    cudaFuncSetAttribute(lstm_rec, cudaFuncAttributeMaxDynamicSharedMemorySize, smem);
    lstm_rec<<<128, 256, smem>>>(whh_f, whh_b);

    pool_kernel<<<512, 256>>>(heads, tails);
    ln_kernel<<<512, 256>>>(FEATP, nullptr, ln_g, ln_b, FEAT);

    dim3 gP(1024/128, 512/128);
    gemm_tf32<<<gP, 256, gemm_smem>>>(FEAT, wq, bq, Qm, 512, 1024, 1024);
    gemm_tf32<<<gP, 256, gemm_smem>>>(FEAT, wk, bk, Km, 512, 1024, 1024);
    gemm_tf32<<<gP, 256, gemm_smem>>>(FEAT, wv, bv, Vm, 512, 1024, 1024);

    attn_kernel<<<256, 256>>>(amask);

    gemm_tf32<<<gP, 256, gemm_smem>>>(CTX, wo, bo, TMP, 512, 1024, 1024);
    ln_kernel<<<512, 256>>>(TMP, FEAT, aln_g, aln_b, ATT);

    cls_kernel<<<512, 96>>>(wc, bc, out);
}

// round 4
// speedup vs baseline: 1.2113x; 1.1142x over previous
#include <cuda_runtime.h>
#include <mma.h>
#include <math.h>

using namespace nvcuda;

#define LN_EPS 1e-7f

__device__ float g_XGf[(size_t)16384 * 2048];
__device__ float g_XGb[(size_t)16384 * 2048];
__device__ float g_ENC[(size_t)16 * 1024 * 1024];
__device__ float g_FEATP[512 * 1024];
__device__ float g_FEAT [512 * 1024];
__device__ float g_Qm[512 * 1024];
__device__ float g_Km[512 * 1024];
__device__ float g_Vm[512 * 1024];
__device__ float g_CTX[512 * 1024];
__device__ float g_TMP[512 * 1024];
__device__ float g_ATT[512 * 1024];
__device__ unsigned g_bar_arrive;
__device__ unsigned g_bar_epoch;

// =====================================================================
// TF32 tensor-core GEMM: C[M,N] = A[M,K] * B[N,K]^T + bias[N]
// =====================================================================
#define LDT 36
#define LDC 132

__global__ __launch_bounds__(256) void gemm_tf32(
    const float* __restrict__ A, const float* __restrict__ B,
    const float* __restrict__ bias, float* __restrict__ C,
    int M, int N, int K)
{
    extern __shared__ float smem[];
    float* As = smem;
    float* Bs = smem + 128 * LDT;
    float* Co = smem;

    const int tid = threadIdx.x;
    const int wid = tid >> 5;
    const int brow = blockIdx.y * 128;
    const int bcol = blockIdx.x * 128;
    const int wm = (wid & 3) * 32;
    const int wn = (wid >> 2) * 64;

    wmma::fragment<wmma::accumulator, 16, 16, 8, float> acc[2][4];
#pragma unroll
    for (int i = 0; i < 2; ++i)
#pragma unroll
        for (int j = 0; j < 4; ++j) wmma::fill_fragment(acc[i][j], 0.f);

    const float* Ag = A + (size_t)brow * K;
    const float* Bg = B + (size_t)bcol * K;

    float4 aR[4], bR[4];
#pragma unroll
    for (int p = 0; p < 4; ++p) {
        const int idx = tid + p * 256;
        const int r = idx >> 3, c4 = (idx & 7) * 4;
        aR[p] = *(const float4*)(Ag + (size_t)r * K + c4);
        bR[p] = *(const float4*)(Bg + (size_t)r * K + c4);
    }

    for (int kt = 0; kt < K; kt += 32) {
#pragma unroll
        for (int p = 0; p < 4; ++p) {
            const int idx = tid + p * 256;
            const int r = idx >> 3, c4 = (idx & 7) * 4;
            *(float4*)(As + r * LDT + c4) = aR[p];
            *(float4*)(Bs + r * LDT + c4) = bR[p];
        }
        __syncthreads();
        if (kt + 32 < K) {
#pragma unroll
            for (int p = 0; p < 4; ++p) {
                const int idx = tid + p * 256;
                const int r = idx >> 3, c4 = (idx & 7) * 4;
                aR[p] = *(const float4*)(Ag + (size_t)r * K + kt + 32 + c4);
                bR[p] = *(const float4*)(Bg + (size_t)r * K + kt + 32 + c4);
            }
        }
#pragma unroll
        for (int kk = 0; kk < 32; kk += 8) {
            wmma::fragment<wmma::matrix_a, 16, 16, 8, wmma::precision::tf32, wmma::row_major> af[2];
            wmma::fragment<wmma::matrix_b, 16, 16, 8, wmma::precision::tf32, wmma::col_major> bf[4];
#pragma unroll
            for (int i = 0; i < 2; ++i) {
                wmma::load_matrix_sync(af[i], As + (wm + i * 16) * LDT + kk, LDT);
#pragma unroll
                for (int t = 0; t < af[i].num_elements; ++t)
                    af[i].x[t] = wmma::__float_to_tf32(af[i].x[t]);
            }
#pragma unroll
            for (int j = 0; j < 4; ++j) {
                wmma::load_matrix_sync(bf[j], Bs + (wn + j * 16) * LDT + kk, LDT);
#pragma unroll
                for (int t = 0; t < bf[j].num_elements; ++t)
                    bf[j].x[t] = wmma::__float_to_tf32(bf[j].x[t]);
            }
#pragma unroll
            for (int i = 0; i < 2; ++i)
#pragma unroll
                for (int j = 0; j < 4; ++j)
                    wmma::mma_sync(acc[i][j], af[i], bf[j], acc[i][j]);
        }
        __syncthreads();
    }

#pragma unroll
    for (int i = 0; i < 2; ++i)
#pragma unroll
        for (int j = 0; j < 4; ++j)
            wmma::store_matrix_sync(Co + (wm + i * 16) * LDC + wn + j * 16,
                                    acc[i][j], LDC, wmma::mem_row_major);
    __syncthreads();

    for (int idx = tid; idx < 128 * 32; idx += 256) {
        const int r = idx >> 5, c4 = (idx & 31) * 4;
        float4 v = *(float4*)(Co + r * LDC + c4);
        v.x += bias[bcol + c4 + 0];
        v.y += bias[bcol + c4 + 1];
        v.z += bias[bcol + c4 + 2];
        v.w += bias[bcol + c4 + 3];
        *(float4*)(C + (size_t)(brow + r) * N + bcol + c4) = v;
    }
}

// =====================================================================
// Persistent bi-LSTM recurrence, tensor-core matvec.
// 128 CTAs = 2 dirs x 64 groups (8 hidden units -> 32 gate cols each).
// Per step: h_prev[16,512] (smem, row-major) x W[32,512] (smem) via
// wmma m16n16k8 tf32: 8 warps = 2 n-tiles x 4 k-groups (16 k-tiles each),
// partial-fragment reduce in smem, gate math, grid barrier.
// =====================================================================
#define LDW 516   // ws row pitch (c-major, k contiguous)
#define LDH 520   // hs row pitch (batch-major, k contiguous)
#define LDR 20    // red row pitch

__device__ __forceinline__ float sigmoidf_(float x) { return 1.f / (1.f + expf(-x)); }

__global__ __launch_bounds__(256) void lstm_rec(
    const float* __restrict__ whh_f, const float* __restrict__ whh_b)
{
    extern __shared__ float sm[];
    float* ws  = sm;                     // [32][LDW]
    float* hs  = ws + 32 * LDW;          // [16][LDH]
    float* red = hs + 16 * LDH;          // [8][16][LDR]
    float* Gs  = red + 8 * 16 * LDR;     // [512] = [16 batch][32 col]
    float* cst = Gs + 512;               // [128]
    __shared__ unsigned s_base;

    const int tid = threadIdx.x;
    const int wid = tid >> 5;
    const int dir = blockIdx.x & 1;
    const int grp = blockIdx.x >> 1;
    const float* whh = dir ? whh_b : whh_f;
    const float* xg  = dir ? g_XGb : g_XGf;

    // stage recurrent weights: ws[c][k], c = gate*8+u -> w_hh row gate*512+grp*8+u
    for (int idx = tid; idx < 32 * 512; idx += 256) {
        int c = idx >> 9, k = idx & 511;
        int j = (c >> 3) * 512 + grp * 8 + (c & 7);
        ws[c * LDW + k] = whh[(size_t)j * 512 + k];
    }
    if (tid < 128) cst[tid] = 0.f;
    if (tid == 0) s_base = atomicAdd(&g_bar_epoch, 0u);
    __syncthreads();
    const unsigned base = s_base;

    const int ntile = wid & 1;        // 0/1 -> cols [0,16) / [16,32)
    const int kgrp  = wid >> 1;       // 0..3 -> k range [kgrp*128, +128)

    for (int s = 0; s < 1024; ++s) {
        const int tcur = dir ? (1023 - s) : s;

        // ---- stage h_prev[16][512] row-major ----
        if (s == 0) {
            for (int idx = tid; idx < 16 * LDH; idx += 256) hs[idx] = 0.f;
        } else {
            const int tprev = dir ? (tcur + 1) : (tcur - 1);
            const int b  = tid >> 4;
            const int k0 = (tid & 15) * 32;
            const float* src = g_ENC + ((size_t)b * 1024 + tprev) * 1024 + dir * 512 + k0;
            float* dst = hs + b * LDH + k0;
#pragma unroll
            for (int j = 0; j < 32; j += 4)
                *(float4*)(dst + j) = *(const float4*)(src + j);
        }
        __syncthreads();

        // ---- tensor matvec: acc[16,16] over 16 k-tiles ----
        wmma::fragment<wmma::accumulator, 16, 16, 8, float> acc;
        wmma::fill_fragment(acc, 0.f);
#pragma unroll 4
        for (int kt = 0; kt < 16; ++kt) {
            const int k0 = kgrp * 128 + kt * 8;
            wmma::fragment<wmma::matrix_a, 16, 16, 8, wmma::precision::tf32, wmma::row_major> af;
            wmma::fragment<wmma::matrix_b, 16, 16, 8, wmma::precision::tf32, wmma::col_major> bf;
            wmma::load_matrix_sync(af, hs + k0, LDH);
#pragma unroll
            for (int t = 0; t < af.num_elements; ++t)
                af.x[t] = wmma::__float_to_tf32(af.x[t]);
            wmma::load_matrix_sync(bf, ws + ntile * 16 * LDW + k0, LDW);
#pragma unroll
            for (int t = 0; t < bf.num_elements; ++t)
                bf.x[t] = wmma::__float_to_tf32(bf.x[t]);
            wmma::mma_sync(acc, af, bf, acc);
        }
        wmma::store_matrix_sync(red + wid * 16 * LDR, acc, LDR, wmma::mem_row_major);
        __syncthreads();

        // ---- reduce 4 k-partials -> Gs[16][32] ----
#pragma unroll
        for (int rep = 0; rep < 2; ++rep) {
            const int o = tid + rep * 256;
            const int m = o >> 5, c = o & 31;
            const int nt = c >> 4, nn = c & 15;
            float sum = 0.f;
#pragma unroll
            for (int p = 0; p < 4; ++p)
                sum += red[(p * 2 + nt) * 16 * LDR + m * LDR + nn];
            Gs[o] = sum;
        }
        __syncthreads();

        // ---- gate math + h write ----
        if (tid < 128) {
            const int b = tid >> 3, u = tid & 7;
            const size_t xbase = ((size_t)b * 1024 + tcur) * 2048 + grp * 8 + u;
            const float gi = Gs[b*32 +  0 + u] + xg[xbase       ];
            const float gf = Gs[b*32 +  8 + u] + xg[xbase +  512];
            const float gg = Gs[b*32 + 16 + u] + xg[xbase + 1024];
            const float go = Gs[b*32 + 24 + u] + xg[xbase + 1536];
            const float cn = sigmoidf_(gf) * cst[tid] + sigmoidf_(gi) * tanhf(gg);
            cst[tid] = cn;
            g_ENC[((size_t)b*1024 + tcur)*1024 + dir*512 + grp*8 + u] = sigmoidf_(go) * tanhf(cn);
            __threadfence();
        }
        __syncthreads();

        // ---- grid barrier ----
        if (tid == 0) {
            unsigned a = atomicAdd(&g_bar_arrive, 1u);
            if (a == gridDim.x - 1) {
                atomicExch(&g_bar_arrive, 0u);
                __threadfence();
                atomicAdd(&g_bar_epoch, 1u);
            } else {
                volatile unsigned* ep = &g_bar_epoch;
                while (*ep - base < (unsigned)(s + 1)) { }
                __threadfence();
            }
        }
        __syncthreads();
    }
}

// ---------------- span mean pooling ----------------
__global__ __launch_bounds__(256) void pool_kernel(
    const int* __restrict__ heads, const int* __restrict__ tails)
{
    const int bs = blockIdx.x;
    const int b = bs >> 5;
    int lo = heads[bs] + 1, hi = tails[bs];
    if (lo < 0) lo = 0;
    if (hi > 1024) hi = 1024;
    int cnt = hi - lo; if (cnt < 1) cnt = 1;
    const float inv = 1.f / (float)cnt;
    const int h0 = threadIdx.x * 4;
    float ax = 0.f, ay = 0.f, az = 0.f, aw = 0.f;
    for (int t = lo; t < hi; ++t) {
        const float4 v = *(const float4*)(g_ENC + ((size_t)b*1024 + t)*1024 + h0);
        ax += v.x; ay += v.y; az += v.z; aw += v.w;
    }
    float4 o; o.x = ax*inv; o.y = ay*inv; o.z = az*inv; o.w = aw*inv;
    *(float4*)(g_FEATP + (size_t)bs*1024 + h0) = o;
}

// ---------------- row LayerNorm (optional residual) ----------------
__global__ __launch_bounds__(256) void ln_kernel(
    const float* __restrict__ X, const float* __restrict__ R,
    const float* __restrict__ gam, const float* __restrict__ bet,
    float* __restrict__ Y)
{
    const int r = blockIdx.x;
    const int tid = threadIdx.x;
    const size_t off = (size_t)r * 1024 + tid * 4;
    float4 v = *(const float4*)(X + off);
    if (R) {
        const float4 rv = *(const float4*)(R + off);
        v.x += rv.x; v.y += rv.y; v.z += rv.z; v.w += rv.w;
    }
    float s  = v.x + v.y + v.z + v.w;
    float ss = v.x*v.x + v.y*v.y + v.z*v.z + v.w*v.w;
#pragma unroll
    for (int o = 16; o; o >>= 1) {
        s  += __shfl_xor_sync(0xffffffffu, s, o);
        ss += __shfl_xor_sync(0xffffffffu, ss, o);
    }
    __shared__ float as_[8], ass_[8];
    if ((tid & 31) == 0) { as_[tid>>5] = s; ass_[tid>>5] = ss; }
    __syncthreads();
    s = 0.f; ss = 0.f;
#pragma unroll
    for (int w = 0; w < 8; ++w) { s += as_[w]; ss += ass_[w]; }
    const float mu  = s * (1.f/1024.f);
    const float var = ss * (1.f/1024.f) - mu*mu;
    const float inv = rsqrtf(var + LN_EPS);
    const int c0 = tid * 4;
    float4 o;
    o.x = (v.x-mu)*inv*gam[c0+0] + bet[c0+0];
    o.y = (v.y-mu)*inv*gam[c0+1] + bet[c0+1];
    o.z = (v.z-mu)*inv*gam[c0+2] + bet[c0+2];
    o.w = (v.w-mu)*inv*gam[c0+3] + bet[c0+3];
    *(float4*)(Y + off) = o;
}

// ---------------- span attention: one CTA per (batch, head) ----------------
__global__ __launch_bounds__(256) void attn_kernel(const int* __restrict__ amask)
{
    const int bh = blockIdx.x;
    const int b = bh >> 4, h = bh & 15;
    __shared__ float qs[2048], ksm[2048], vsm[2048], sc[32*33];
    __shared__ int ms[32];
    const int tid = threadIdx.x;
    for (int idx = tid; idx < 2048; idx += 256) {
        const int s = idx >> 6, d = idx & 63;
        const size_t off = (size_t)(b*32 + s)*1024 + h*64 + d;
        qs[idx] = g_Qm[off]; ksm[idx] = g_Km[off]; vsm[idx] = g_Vm[off];
    }
    if (tid < 32) ms[tid] = amask[b*32 + tid];
    __syncthreads();
    for (int idx = tid; idx < 1024; idx += 256) {
        const int i = idx >> 5, j = idx & 31;
        float d0 = 0.f;
#pragma unroll
        for (int k = 0; k < 64; ++k) d0 += qs[i*64+k] * ksm[j*64+k];
        sc[i*33 + j] = d0 * 0.125f;
    }
    __syncthreads();
    const int w = tid >> 5, l = tid & 31;
    for (int i = w; i < 32; i += 8) {
        const bool valid = (ms[i] != 0) && (ms[l] != 0);
        float v = valid ? sc[i*33 + l] : -3.402823466e38f;
        float mx = v;
#pragma unroll
        for (int o = 16; o; o >>= 1) mx = fmaxf(mx, __shfl_xor_sync(0xffffffffu, mx, o));
        float e = expf(v - mx);
        float sum = e;
#pragma unroll
        for (int o = 16; o; o >>= 1) sum += __shfl_xor_sync(0xffffffffu, sum, o);
        float p = e / sum;
        if (!valid) p = 0.f;
        sc[i*33 + l] = p;
    }
    __syncthreads();
    for (int idx = tid; idx < 2048; idx += 256) {
        const int s = idx >> 6, d = idx & 63;
        float a = 0.f;
#pragma unroll
        for (int j = 0; j < 32; ++j) a += sc[s*33 + j] * vsm[j*64 + d];
        g_CTX[(size_t)(b*32 + s)*1024 + h*64 + d] = a;
    }
}

// ---------------- classifier ----------------
__global__ __launch_bounds__(96) void cls_kernel(
    const float* __restrict__ wc, const float* __restrict__ bc,
    float* __restrict__ out)
{
    const int r = blockIdx.x;
    const int lbl = threadIdx.x >> 5, lane = threadIdx.x & 31;
    const float* a = g_ATT + (size_t)r * 1024 + lane * 32;
    const float* w = wc + (size_t)lbl * 1024 + lane * 32;
    float s = 0.f;
#pragma unroll
    for (int k = 0; k < 32; ++k) s += a[k] * w[k];
#pragma unroll
    for (int o = 16; o; o >>= 1) s += __shfl_xor_sync(0xffffffffu, s, o);
    if (lane == 0) out[r * 3 + lbl] = s + bc[lbl];
}

extern "C" void kernel_launch(void* const* d_in, const int* in_sizes, int n_in,
                              void* d_out, int out_size) {
    const float* hs    = (const float*)d_in[0];
    const float* wih_f = (const float*)d_in[1];
    const float* whh_f = (const float*)d_in[2];
    const float* b_f   = (const float*)d_in[3];
    const float* wih_b = (const float*)d_in[4];
    const float* whh_b = (const float*)d_in[5];
    const float* b_b   = (const float*)d_in[6];
    const float* ln_g  = (const float*)d_in[7];
    const float* ln_b  = (const float*)d_in[8];
    const float* wq = (const float*)d_in[9];  const float* bq = (const float*)d_in[10];
    const float* wk = (const float*)d_in[11]; const float* bk = (const float*)d_in[12];
    const float* wv = (const float*)d_in[13]; const float* bv = (const float*)d_in[14];
    const float* wo = (const float*)d_in[15]; const float* bo = (const float*)d_in[16];
    const float* aln_g = (const float*)d_in[17];
    const float* aln_b = (const float*)d_in[18];
    const float* wc = (const float*)d_in[19]; const float* bc = (const float*)d_in[20];
    const int* heads = (const int*)d_in[21];
    const int* tails = (const int*)d_in[22];
    const int* amask = (const int*)d_in[23];
    float* out = (float*)d_out;

    float *XGf, *XGb, *FEATP, *FEAT, *Qm, *Km, *Vm, *CTX, *TMP, *ATT;
    cudaGetSymbolAddress((void**)&XGf, g_XGf);
    cudaGetSymbolAddress((void**)&XGb, g_XGb);
    cudaGetSymbolAddress((void**)&FEATP, g_FEATP);
    cudaGetSymbolAddress((void**)&FEAT, g_FEAT);
    cudaGetSymbolAddress((void**)&Qm, g_Qm);
    cudaGetSymbolAddress((void**)&Km, g_Km);
    cudaGetSymbolAddress((void**)&Vm, g_Vm);
    cudaGetSymbolAddress((void**)&CTX, g_CTX);
    cudaGetSymbolAddress((void**)&TMP, g_TMP);
    cudaGetSymbolAddress((void**)&ATT, g_ATT);

    const int gemm_smem = 128 * LDC * sizeof(float);
    cudaFuncSetAttribute(gemm_tf32, cudaFuncAttributeMaxDynamicSharedMemorySize, gemm_smem);

    dim3 gXG(2048/128, 16384/128);
    gemm_tf32<<<gXG, 256, gemm_smem>>>(hs, wih_f, b_f, XGf, 16384, 2048, 1024);
    gemm_tf32<<<gXG, 256, gemm_smem>>>(hs, wih_b, b_b, XGb, 16384, 2048, 1024);

    const int lstm_smem = (32*LDW + 16*LDH + 8*16*LDR + 512 + 128) * sizeof(float);
    cudaFuncSetAttribute(lstm_rec, cudaFuncAttributeMaxDynamicSharedMemorySize, lstm_smem);
    lstm_rec<<<128, 256, lstm_smem>>>(whh_f, whh_b);

    pool_kernel<<<512, 256>>>(heads, tails);
    ln_kernel<<<512, 256>>>(FEATP, nullptr, ln_g, ln_b, FEAT);

    dim3 gP(1024/128, 512/128);
    gemm_tf32<<<gP, 256, gemm_smem>>>(FEAT, wq, bq, Qm, 512, 1024, 1024);
    gemm_tf32<<<gP, 256, gemm_smem>>>(FEAT, wk, bk, Km, 512, 1024, 1024);
    gemm_tf32<<<gP, 256, gemm_smem>>>(FEAT, wv, bv, Vm, 512, 1024, 1024);

    attn_kernel<<<256, 256>>>(amask);

    gemm_tf32<<<gP, 256, gemm_smem>>>(CTX, wo, bo, TMP, 512, 1024, 1024);
    ln_kernel<<<512, 256>>>(TMP, FEAT, aln_g, aln_b, ATT);

    cls_kernel<<<512, 96>>>(wc, bc, out);
}

// round 5
// speedup vs baseline: 1.5072x; 1.2443x over previous
#include <cuda_runtime.h>
#include <mma.h>
#include <math.h>

using namespace nvcuda;

#define LN_EPS 1e-7f

__device__ float g_XGf[(size_t)16384 * 2048];
__device__ float g_XGb[(size_t)16384 * 2048];
__device__ float g_ENC[(size_t)16 * 1024 * 1024];
__device__ float g_FEATP[512 * 1024];
__device__ float g_FEAT [512 * 1024];
__device__ float g_Qm[512 * 1024];
__device__ float g_Km[512 * 1024];
__device__ float g_Vm[512 * 1024];
__device__ float g_CTX[512 * 1024];
__device__ float g_TMP[512 * 1024];
__device__ float g_ATT[512 * 1024];
__device__ unsigned g_cnt[64];   // [dir*32]: monotonic arrival counters, 128B apart

// =====================================================================
// TF32 tensor-core GEMM: C[M,N] = A[M,K] * B[N,K]^T + bias[N]
// =====================================================================
#define LDT 36
#define LDC 132

__global__ __launch_bounds__(256) void gemm_tf32(
    const float* __restrict__ A, const float* __restrict__ B,
    const float* __restrict__ bias, float* __restrict__ C,
    int M, int N, int K)
{
    extern __shared__ float smem[];
    float* As = smem;
    float* Bs = smem + 128 * LDT;
    float* Co = smem;

    const int tid = threadIdx.x;
    const int wid = tid >> 5;
    const int brow = blockIdx.y * 128;
    const int bcol = blockIdx.x * 128;
    const int wm = (wid & 3) * 32;
    const int wn = (wid >> 2) * 64;

    wmma::fragment<wmma::accumulator, 16, 16, 8, float> acc[2][4];
#pragma unroll
    for (int i = 0; i < 2; ++i)
#pragma unroll
        for (int j = 0; j < 4; ++j) wmma::fill_fragment(acc[i][j], 0.f);

    const float* Ag = A + (size_t)brow * K;
    const float* Bg = B + (size_t)bcol * K;

    float4 aR[4], bR[4];
#pragma unroll
    for (int p = 0; p < 4; ++p) {
        const int idx = tid + p * 256;
        const int r = idx >> 3, c4 = (idx & 7) * 4;
        aR[p] = *(const float4*)(Ag + (size_t)r * K + c4);
        bR[p] = *(const float4*)(Bg + (size_t)r * K + c4);
    }

    for (int kt = 0; kt < K; kt += 32) {
#pragma unroll
        for (int p = 0; p < 4; ++p) {
            const int idx = tid + p * 256;
            const int r = idx >> 3, c4 = (idx & 7) * 4;
            *(float4*)(As + r * LDT + c4) = aR[p];
            *(float4*)(Bs + r * LDT + c4) = bR[p];
        }
        __syncthreads();
        if (kt + 32 < K) {
#pragma unroll
            for (int p = 0; p < 4; ++p) {
                const int idx = tid + p * 256;
                const int r = idx >> 3, c4 = (idx & 7) * 4;
                aR[p] = *(const float4*)(Ag + (size_t)r * K + kt + 32 + c4);
                bR[p] = *(const float4*)(Bg + (size_t)r * K + kt + 32 + c4);
            }
        }
#pragma unroll
        for (int kk = 0; kk < 32; kk += 8) {
            wmma::fragment<wmma::matrix_a, 16, 16, 8, wmma::precision::tf32, wmma::row_major> af[2];
            wmma::fragment<wmma::matrix_b, 16, 16, 8, wmma::precision::tf32, wmma::col_major> bf[4];
#pragma unroll
            for (int i = 0; i < 2; ++i) {
                wmma::load_matrix_sync(af[i], As + (wm + i * 16) * LDT + kk, LDT);
#pragma unroll
                for (int t = 0; t < af[i].num_elements; ++t)
                    af[i].x[t] = wmma::__float_to_tf32(af[i].x[t]);
            }
#pragma unroll
            for (int j = 0; j < 4; ++j) {
                wmma::load_matrix_sync(bf[j], Bs + (wn + j * 16) * LDT + kk, LDT);
#pragma unroll
                for (int t = 0; t < bf[j].num_elements; ++t)
                    bf[j].x[t] = wmma::__float_to_tf32(bf[j].x[t]);
            }
#pragma unroll
            for (int i = 0; i < 2; ++i)
#pragma unroll
                for (int j = 0; j < 4; ++j)
                    wmma::mma_sync(acc[i][j], af[i], bf[j], acc[i][j]);
        }
        __syncthreads();
    }

#pragma unroll
    for (int i = 0; i < 2; ++i)
#pragma unroll
        for (int j = 0; j < 4; ++j)
            wmma::store_matrix_sync(Co + (wm + i * 16) * LDC + wn + j * 16,
                                    acc[i][j], LDC, wmma::mem_row_major);
    __syncthreads();

    for (int idx = tid; idx < 128 * 32; idx += 256) {
        const int r = idx >> 5, c4 = (idx & 31) * 4;
        float4 v = *(float4*)(Co + r * LDC + c4);
        v.x += bias[bcol + c4 + 0];
        v.y += bias[bcol + c4 + 1];
        v.z += bias[bcol + c4 + 2];
        v.w += bias[bcol + c4 + 3];
        *(float4*)(C + (size_t)(brow + r) * N + bcol + c4) = v;
    }
}

// =====================================================================
// Barrier counter reset (runs before lstm_rec every replay)
// =====================================================================
__global__ void bar_reset() { g_cnt[0] = 0; g_cnt[32] = 0; }

// =====================================================================
// Persistent bi-LSTM recurrence, tensor-core matvec.
// 128 CTAs = 2 independent sync domains (dirs) x 64 groups.
// Barrier: monotonic counter, red.release.gpu arrive / ld.acquire.gpu poll.
// =====================================================================
#define LDW 516
#define LDH 520
#define LDR 20

__device__ __forceinline__ float sigmoidf_(float x) { return 1.f / (1.f + expf(-x)); }

__global__ __launch_bounds__(256) void lstm_rec(
    const float* __restrict__ whh_f, const float* __restrict__ whh_b)
{
    extern __shared__ float sm[];
    float* ws  = sm;                     // [32][LDW]
    float* hs  = ws + 32 * LDW;          // [16][LDH]
    float* red = hs + 16 * LDH;          // [8][16][LDR]
    float* Gs  = red + 8 * 16 * LDR;     // [512]
    float* cst = Gs + 512;               // [128]

    const int tid = threadIdx.x;
    const int wid = tid >> 5;
    const int dir = blockIdx.x & 1;
    const int grp = blockIdx.x >> 1;
    const float* whh = dir ? whh_b : whh_f;
    const float* xg  = dir ? g_XGb : g_XGf;
    unsigned* cnt = &g_cnt[dir * 32];

    for (int idx = tid; idx < 32 * 512; idx += 256) {
        int c = idx >> 9, k = idx & 511;
        int j = (c >> 3) * 512 + grp * 8 + (c & 7);
        ws[c * LDW + k] = whh[(size_t)j * 512 + k];
    }
    if (tid < 128) cst[tid] = 0.f;
    __syncthreads();

    const int ntile = wid & 1;
    const int kgrp  = wid >> 1;
    const int gb = tid >> 3, gu = tid & 7;   // gate-phase indices (tid<128)

    for (int s = 0; s < 1024; ++s) {
        const int tcur = dir ? (1023 - s) : s;

        // ---- prefetch input-gate terms (off critical path) ----
        float xgi, xgf2, xgg, xgo;
        if (tid < 128) {
            const size_t xbase = ((size_t)gb * 1024 + tcur) * 2048 + grp * 8 + gu;
            xgi  = xg[xbase       ];
            xgf2 = xg[xbase +  512];
            xgg  = xg[xbase + 1024];
            xgo  = xg[xbase + 1536];
        }

        // ---- stage h_prev[16][512] ----
        if (s == 0) {
            for (int idx = tid; idx < 16 * LDH; idx += 256) hs[idx] = 0.f;
        } else {
            const int tprev = dir ? (tcur + 1) : (tcur - 1);
            const int b  = tid >> 4;
            const int k0 = (tid & 15) * 32;
            const float* src = g_ENC + ((size_t)b * 1024 + tprev) * 1024 + dir * 512 + k0;
            float* dst = hs + b * LDH + k0;
#pragma unroll
            for (int j = 0; j < 32; j += 4)
                *(float4*)(dst + j) = *(const float4*)(src + j);
        }
        __syncthreads();

        // ---- tensor matvec ----
        wmma::fragment<wmma::accumulator, 16, 16, 8, float> acc;
        wmma::fill_fragment(acc, 0.f);
#pragma unroll 4
        for (int kt = 0; kt < 16; ++kt) {
            const int k0 = kgrp * 128 + kt * 8;
            wmma::fragment<wmma::matrix_a, 16, 16, 8, wmma::precision::tf32, wmma::row_major> af;
            wmma::fragment<wmma::matrix_b, 16, 16, 8, wmma::precision::tf32, wmma::col_major> bf;
            wmma::load_matrix_sync(af, hs + k0, LDH);
#pragma unroll
            for (int t = 0; t < af.num_elements; ++t)
                af.x[t] = wmma::__float_to_tf32(af.x[t]);
            wmma::load_matrix_sync(bf, ws + ntile * 16 * LDW + k0, LDW);
#pragma unroll
            for (int t = 0; t < bf.num_elements; ++t)
                bf.x[t] = wmma::__float_to_tf32(bf.x[t]);
            wmma::mma_sync(acc, af, bf, acc);
        }
        wmma::store_matrix_sync(red + wid * 16 * LDR, acc, LDR, wmma::mem_row_major);
        __syncthreads();

        // ---- reduce 4 k-partials -> Gs[16][32] ----
#pragma unroll
        for (int rep = 0; rep < 2; ++rep) {
            const int o = tid + rep * 256;
            const int m = o >> 5, c = o & 31;
            const int nt = c >> 4, nn = c & 15;
            float sum = 0.f;
#pragma unroll
            for (int p = 0; p < 4; ++p)
                sum += red[(p * 2 + nt) * 16 * LDR + m * LDR + nn];
            Gs[o] = sum;
        }
        __syncthreads();

        // ---- gate math + h write ----
        if (tid < 128) {
            const float gi = Gs[gb*32 +  0 + gu] + xgi;
            const float gf = Gs[gb*32 +  8 + gu] + xgf2;
            const float gg = Gs[gb*32 + 16 + gu] + xgg;
            const float go = Gs[gb*32 + 24 + gu] + xgo;
            const float cn = sigmoidf_(gf) * cst[tid] + sigmoidf_(gi) * tanhf(gg);
            cst[tid] = cn;
            g_ENC[((size_t)gb*1024 + tcur)*1024 + dir*512 + grp*8 + gu] = sigmoidf_(go) * tanhf(cn);
        }
        __syncthreads();

        // ---- release/acquire monotonic barrier (per-direction domain) ----
        if (tid == 0) {
            asm volatile("red.release.gpu.global.add.u32 [%0], 1;" :: "l"(cnt) : "memory");
            const unsigned tgt = (unsigned)(s + 1) * 64u;
            unsigned v;
            do {
                asm volatile("ld.acquire.gpu.global.b32 %0, [%1];" : "=r"(v) : "l"(cnt));
            } while (v < tgt);
        }
        __syncthreads();
    }
}

// ---------------- span mean pooling ----------------
__global__ __launch_bounds__(256) void pool_kernel(
    const int* __restrict__ heads, const int* __restrict__ tails)
{
    const int bs = blockIdx.x;
    const int b = bs >> 5;
    int lo = heads[bs] + 1, hi = tails[bs];
    if (lo < 0) lo = 0;
    if (hi > 1024) hi = 1024;
    int cnt = hi - lo; if (cnt < 1) cnt = 1;
    const float inv = 1.f / (float)cnt;
    const int h0 = threadIdx.x * 4;
    float ax = 0.f, ay = 0.f, az = 0.f, aw = 0.f;
    for (int t = lo; t < hi; ++t) {
        const float4 v = *(const float4*)(g_ENC + ((size_t)b*1024 + t)*1024 + h0);
        ax += v.x; ay += v.y; az += v.z; aw += v.w;
    }
    float4 o; o.x = ax*inv; o.y = ay*inv; o.z = az*inv; o.w = aw*inv;
    *(float4*)(g_FEATP + (size_t)bs*1024 + h0) = o;
}

// ---------------- row LayerNorm (optional residual) ----------------
__global__ __launch_bounds__(256) void ln_kernel(
    const float* __restrict__ X, const float* __restrict__ R,
    const float* __restrict__ gam, const float* __restrict__ bet,
    float* __restrict__ Y)
{
    const int r = blockIdx.x;
    const int tid = threadIdx.x;
    const size_t off = (size_t)r * 1024 + tid * 4;
    float4 v = *(const float4*)(X + off);
    if (R) {
        const float4 rv = *(const float4*)(R + off);
        v.x += rv.x; v.y += rv.y; v.z += rv.z; v.w += rv.w;
    }
    float s  = v.x + v.y + v.z + v.w;
    float ss = v.x*v.x + v.y*v.y + v.z*v.z + v.w*v.w;
#pragma unroll
    for (int o = 16; o; o >>= 1) {
        s  += __shfl_xor_sync(0xffffffffu, s, o);
        ss += __shfl_xor_sync(0xffffffffu, ss, o);
    }
    __shared__ float as_[8], ass_[8];
    if ((tid & 31) == 0) { as_[tid>>5] = s; ass_[tid>>5] = ss; }
    __syncthreads();
    s = 0.f; ss = 0.f;
#pragma unroll
    for (int w = 0; w < 8; ++w) { s += as_[w]; ss += ass_[w]; }
    const float mu  = s * (1.f/1024.f);
    const float var = ss * (1.f/1024.f) - mu*mu;
    const float inv = rsqrtf(var + LN_EPS);
    const int c0 = tid * 4;
    float4 o;
    o.x = (v.x-mu)*inv*gam[c0+0] + bet[c0+0];
    o.y = (v.y-mu)*inv*gam[c0+1] + bet[c0+1];
    o.z = (v.z-mu)*inv*gam[c0+2] + bet[c0+2];
    o.w = (v.w-mu)*inv*gam[c0+3] + bet[c0+3];
    *(float4*)(Y + off) = o;
}

// ---------------- span attention ----------------
__global__ __launch_bounds__(256) void attn_kernel(const int* __restrict__ amask)
{
    const int bh = blockIdx.x;
    const int b = bh >> 4, h = bh & 15;
    __shared__ float qs[2048], ksm[2048], vsm[2048], sc[32*33];
    __shared__ int ms[32];
    const int tid = threadIdx.x;
    for (int idx = tid; idx < 2048; idx += 256) {
        const int s = idx >> 6, d = idx & 63;
        const size_t off = (size_t)(b*32 + s)*1024 + h*64 + d;
        qs[idx] = g_Qm[off]; ksm[idx] = g_Km[off]; vsm[idx] = g_Vm[off];
    }
    if (tid < 32) ms[tid] = amask[b*32 + tid];
    __syncthreads();
    for (int idx = tid; idx < 1024; idx += 256) {
        const int i = idx >> 5, j = idx & 31;
        float d0 = 0.f;
#pragma unroll
        for (int k = 0; k < 64; ++k) d0 += qs[i*64+k] * ksm[j*64+k];
        sc[i*33 + j] = d0 * 0.125f;
    }
    __syncthreads();
    const int w = tid >> 5, l = tid & 31;
    for (int i = w; i < 32; i += 8) {
        const bool valid = (ms[i] != 0) && (ms[l] != 0);
        float v = valid ? sc[i*33 + l] : -3.402823466e38f;
        float mx = v;
#pragma unroll
        for (int o = 16; o; o >>= 1) mx = fmaxf(mx, __shfl_xor_sync(0xffffffffu, mx, o));
        float e = expf(v - mx);
        float sum = e;
#pragma unroll
        for (int o = 16; o; o >>= 1) sum += __shfl_xor_sync(0xffffffffu, sum, o);
        float p = e / sum;
        if (!valid) p = 0.f;
        sc[i*33 + l] = p;
    }
    __syncthreads();
    for (int idx = tid; idx < 2048; idx += 256) {
        const int s = idx >> 6, d = idx & 63;
        float a = 0.f;
#pragma unroll
        for (int j = 0; j < 32; ++j) a += sc[s*33 + j] * vsm[j*64 + d];
        g_CTX[(size_t)(b*32 + s)*1024 + h*64 + d] = a;
    }
}

// ---------------- classifier ----------------
__global__ __launch_bounds__(96) void cls_kernel(
    const float* __restrict__ wc, const float* __restrict__ bc,
    float* __restrict__ out)
{
    const int r = blockIdx.x;
    const int lbl = threadIdx.x >> 5, lane = threadIdx.x & 31;
    const float* a = g_ATT + (size_t)r * 1024 + lane * 32;
    const float* w = wc + (size_t)lbl * 1024 + lane * 32;
    float s = 0.f;
#pragma unroll
    for (int k = 0; k < 32; ++k) s += a[k] * w[k];
#pragma unroll
    for (int o = 16; o; o >>= 1) s += __shfl_xor_sync(0xffffffffu, s, o);
    if (lane == 0) out[r * 3 + lbl] = s + bc[lbl];
}

extern "C" void kernel_launch(void* const* d_in, const int* in_sizes, int n_in,
                              void* d_out, int out_size) {
    const float* hs    = (const float*)d_in[0];
    const float* wih_f = (const float*)d_in[1];
    const float* whh_f = (const float*)d_in[2];
    const float* b_f   = (const float*)d_in[3];
    const float* wih_b = (const float*)d_in[4];
    const float* whh_b = (const float*)d_in[5];
    const float* b_b   = (const float*)d_in[6];
    const float* ln_g  = (const float*)d_in[7];
    const float* ln_b  = (const float*)d_in[8];
    const float* wq = (const float*)d_in[9];  const float* bq = (const float*)d_in[10];
    const float* wk = (const float*)d_in[11]; const float* bk = (const float*)d_in[12];
    const float* wv = (const float*)d_in[13]; const float* bv = (const float*)d_in[14];
    const float* wo = (const float*)d_in[15]; const float* bo = (const float*)d_in[16];
    const float* aln_g = (const float*)d_in[17];
    const float* aln_b = (const float*)d_in[18];
    const float* wc = (const float*)d_in[19]; const float* bc = (const float*)d_in[20];
    const int* heads = (const int*)d_in[21];
    const int* tails = (const int*)d_in[22];
    const int* amask = (const int*)d_in[23];
    float* out = (float*)d_out;

    float *XGf, *XGb, *FEATP, *FEAT, *Qm, *Km, *Vm, *CTX, *TMP, *ATT;
    cudaGetSymbolAddress((void**)&XGf, g_XGf);
    cudaGetSymbolAddress((void**)&XGb, g_XGb);
    cudaGetSymbolAddress((void**)&FEATP, g_FEATP);
    cudaGetSymbolAddress((void**)&FEAT, g_FEAT);
    cudaGetSymbolAddress((void**)&Qm, g_Qm);
    cudaGetSymbolAddress((void**)&Km, g_Km);
    cudaGetSymbolAddress((void**)&Vm, g_Vm);
    cudaGetSymbolAddress((void**)&CTX, g_CTX);
    cudaGetSymbolAddress((void**)&TMP, g_TMP);
    cudaGetSymbolAddress((void**)&ATT, g_ATT);

    const int gemm_smem = 128 * LDC * sizeof(float);
    cudaFuncSetAttribute(gemm_tf32, cudaFuncAttributeMaxDynamicSharedMemorySize, gemm_smem);

    dim3 gXG(2048/128, 16384/128);
    gemm_tf32<<<gXG, 256, gemm_smem>>>(hs, wih_f, b_f, XGf, 16384, 2048, 1024);
    gemm_tf32<<<gXG, 256, gemm_smem>>>(hs, wih_b, b_b, XGb, 16384, 2048, 1024);

    bar_reset<<<1, 1>>>();
    const int lstm_smem = (32*LDW + 16*LDH + 8*16*LDR + 512 + 128) * sizeof(float);
    cudaFuncSetAttribute(lstm_rec, cudaFuncAttributeMaxDynamicSharedMemorySize, lstm_smem);
    lstm_rec<<<128, 256, lstm_smem>>>(whh_f, whh_b);

    pool_kernel<<<512, 256>>>(heads, tails);
    ln_kernel<<<512, 256>>>(FEATP, nullptr, ln_g, ln_b, FEAT);

    dim3 gP(1024/128, 512/128);
    gemm_tf32<<<gP, 256, gemm_smem>>>(FEAT, wq, bq, Qm, 512, 1024, 1024);
    gemm_tf32<<<gP, 256, gemm_smem>>>(FEAT, wk, bk, Km, 512, 1024, 1024);
    gemm_tf32<<<gP, 256, gemm_smem>>>(FEAT, wv, bv, Vm, 512, 1024, 1024);

    attn_kernel<<<256, 256>>>(amask);

    gemm_tf32<<<gP, 256, gemm_smem>>>(CTX, wo, bo, TMP, 512, 1024, 1024);
    ln_kernel<<<512, 256>>>(TMP, FEAT, aln_g, aln_b, ATT);

    cls_kernel<<<512, 96>>>(wc, bc, out);
}

// round 6
// speedup vs baseline: 1.5073x; 1.0001x over previous
#include <cuda_runtime.h>
#include <mma.h>
#include <math.h>

using namespace nvcuda;

#define LN_EPS 1e-7f

__device__ float g_XGf[(size_t)16384 * 2048];
__device__ float g_XGb[(size_t)16384 * 2048];
__device__ float g_ENC[(size_t)16 * 1024 * 1024];
__device__ float g_FEATP[512 * 1024];
__device__ float g_FEAT [512 * 1024];
__device__ float g_Qm[512 * 1024];
__device__ float g_Km[512 * 1024];
__device__ float g_Vm[512 * 1024];
__device__ float g_CTX[512 * 1024];
__device__ float g_TMP[512 * 1024];
__device__ float g_ATT[512 * 1024];
__device__ unsigned g_cnt[64];   // [dir*32]: monotonic arrival counters

// =====================================================================
// TF32 tensor-core GEMM: C[M,N] = A[M,K] * B[N,K]^T + bias[N]
// =====================================================================
#define LDT 36
#define LDC 132

__global__ __launch_bounds__(256) void gemm_tf32(
    const float* __restrict__ A, const float* __restrict__ B,
    const float* __restrict__ bias, float* __restrict__ C,
    int M, int N, int K)
{
    extern __shared__ float smem[];
    float* As = smem;
    float* Bs = smem + 128 * LDT;
    float* Co = smem;

    const int tid = threadIdx.x;
    const int wid = tid >> 5;
    const int brow = blockIdx.y * 128;
    const int bcol = blockIdx.x * 128;
    const int wm = (wid & 3) * 32;
    const int wn = (wid >> 2) * 64;

    wmma::fragment<wmma::accumulator, 16, 16, 8, float> acc[2][4];
#pragma unroll
    for (int i = 0; i < 2; ++i)
#pragma unroll
        for (int j = 0; j < 4; ++j) wmma::fill_fragment(acc[i][j], 0.f);

    const float* Ag = A + (size_t)brow * K;
    const float* Bg = B + (size_t)bcol * K;

    float4 aR[4], bR[4];
#pragma unroll
    for (int p = 0; p < 4; ++p) {
        const int idx = tid + p * 256;
        const int r = idx >> 3, c4 = (idx & 7) * 4;
        aR[p] = *(const float4*)(Ag + (size_t)r * K + c4);
        bR[p] = *(const float4*)(Bg + (size_t)r * K + c4);
    }

    for (int kt = 0; kt < K; kt += 32) {
#pragma unroll
        for (int p = 0; p < 4; ++p) {
            const int idx = tid + p * 256;
            const int r = idx >> 3, c4 = (idx & 7) * 4;
            *(float4*)(As + r * LDT + c4) = aR[p];
            *(float4*)(Bs + r * LDT + c4) = bR[p];
        }
        __syncthreads();
        if (kt + 32 < K) {
#pragma unroll
            for (int p = 0; p < 4; ++p) {
                const int idx = tid + p * 256;
                const int r = idx >> 3, c4 = (idx & 7) * 4;
                aR[p] = *(const float4*)(Ag + (size_t)r * K + kt + 32 + c4);
                bR[p] = *(const float4*)(Bg + (size_t)r * K + kt + 32 + c4);
            }
        }
#pragma unroll
        for (int kk = 0; kk < 32; kk += 8) {
            wmma::fragment<wmma::matrix_a, 16, 16, 8, wmma::precision::tf32, wmma::row_major> af[2];
            wmma::fragment<wmma::matrix_b, 16, 16, 8, wmma::precision::tf32, wmma::col_major> bf[4];
#pragma unroll
            for (int i = 0; i < 2; ++i) {
                wmma::load_matrix_sync(af[i], As + (wm + i * 16) * LDT + kk, LDT);
#pragma unroll
                for (int t = 0; t < af[i].num_elements; ++t)
                    af[i].x[t] = wmma::__float_to_tf32(af[i].x[t]);
            }
#pragma unroll
            for (int j = 0; j < 4; ++j) {
                wmma::load_matrix_sync(bf[j], Bs + (wn + j * 16) * LDT + kk, LDT);
#pragma unroll
                for (int t = 0; t < bf[j].num_elements; ++t)
                    bf[j].x[t] = wmma::__float_to_tf32(bf[j].x[t]);
            }
#pragma unroll
            for (int i = 0; i < 2; ++i)
#pragma unroll
                for (int j = 0; j < 4; ++j)
                    wmma::mma_sync(acc[i][j], af[i], bf[j], acc[i][j]);
        }
        __syncthreads();
    }

#pragma unroll
    for (int i = 0; i < 2; ++i)
#pragma unroll
        for (int j = 0; j < 4; ++j)
            wmma::store_matrix_sync(Co + (wm + i * 16) * LDC + wn + j * 16,
                                    acc[i][j], LDC, wmma::mem_row_major);
    __syncthreads();

    for (int idx = tid; idx < 128 * 32; idx += 256) {
        const int r = idx >> 5, c4 = (idx & 31) * 4;
        float4 v = *(float4*)(Co + r * LDC + c4);
        v.x += bias[bcol + c4 + 0];
        v.y += bias[bcol + c4 + 1];
        v.z += bias[bcol + c4 + 2];
        v.w += bias[bcol + c4 + 3];
        *(float4*)(C + (size_t)(brow + r) * N + bcol + c4) = v;
    }
}

// =====================================================================
__global__ void bar_reset() { g_cnt[0] = 0; g_cnt[32] = 0; }

// =====================================================================
// Persistent bi-LSTM recurrence, tensor-core matvec.
// 64 CTAs = 2 dirs x 32 groups (16 h-units -> 64 gate cols, c = u*4+gate).
// 512 threads = 16 warps = 4 n-tiles x 4 k-groups.
// Fused reduce+gate phase; xg prefetch overlaps barrier wait.
// =====================================================================
#define LDW 516
#define LDH 520
#define LDR 20

__device__ __forceinline__ float sigmoidf_(float x) { return 1.f / (1.f + expf(-x)); }

__global__ __launch_bounds__(512) void lstm_rec(
    const float* __restrict__ whh_f, const float* __restrict__ whh_b)
{
    extern __shared__ float sm[];
    float* ws  = sm;                     // [64][LDW]   c = u*4+gate
    float* hs  = ws + 64 * LDW;          // [16][LDH]
    float* red = hs + 16 * LDH;          // [16 warps][16][LDR]
    float* cst = red + 16 * 16 * LDR;    // [256] (m*16+u)

    const int tid = threadIdx.x;
    const int wid = tid >> 5;
    const int dir = blockIdx.x & 1;
    const int grp = blockIdx.x >> 1;     // 0..31, units [grp*16, grp*16+16)
    const float* whh = dir ? whh_b : whh_f;
    const float* xg  = dir ? g_XGb : g_XGf;
    unsigned* cnt = &g_cnt[dir * 32];

    // stage recurrent weights: ws[c][k], c=u*4+gate -> row gate*512 + grp*16 + u
    for (int idx = tid; idx < 64 * 512; idx += 512) {
        int c = idx >> 9, k = idx & 511;
        int j = (c & 3) * 512 + grp * 16 + (c >> 2);
        ws[c * LDW + k] = whh[(size_t)j * 512 + k];
    }
    if (tid < 256) cst[tid] = 0.f;
    __syncthreads();

    const int ntile = wid & 3;           // 0..3 -> cols [ntile*16, +16)
    const int kgrp  = wid >> 2;          // 0..3 -> k range [kgrp*128, +128)
    const int gm = tid >> 4, gu = tid & 15;   // gate-phase (tid<256)

    // prefetch xg for step 0
    float xgi, xgf2, xgg, xgo;
    {
        const int t0 = dir ? 1023 : 0;
        if (tid < 256) {
            const size_t xb = ((size_t)gm * 1024 + t0) * 2048 + grp * 16 + gu;
            xgi  = xg[xb          ];
            xgf2 = xg[xb +  512];
            xgg  = xg[xb + 1024];
            xgo  = xg[xb + 1536];
        }
    }

    for (int s = 0; s < 1024; ++s) {
        const int tcur = dir ? (1023 - s) : s;

        // ---- stage h_prev[16][512] ----
        if (s == 0) {
            for (int idx = tid; idx < 16 * LDH; idx += 512) hs[idx] = 0.f;
        } else {
            const int tprev = dir ? (tcur + 1) : (tcur - 1);
            const int b  = tid >> 5;
            const int k0 = (tid & 31) * 16;
            const float* src = g_ENC + ((size_t)b * 1024 + tprev) * 1024 + dir * 512 + k0;
            float* dst = hs + b * LDH + k0;
#pragma unroll
            for (int j = 0; j < 16; j += 4)
                *(float4*)(dst + j) = *(const float4*)(src + j);
        }
        __syncthreads();

        // ---- tensor matvec: per warp 16 k-tiles into one 16x16 acc ----
        wmma::fragment<wmma::accumulator, 16, 16, 8, float> acc;
        wmma::fill_fragment(acc, 0.f);
#pragma unroll 4
        for (int kt = 0; kt < 16; ++kt) {
            const int k0 = kgrp * 128 + kt * 8;
            wmma::fragment<wmma::matrix_a, 16, 16, 8, wmma::precision::tf32, wmma::row_major> af;
            wmma::fragment<wmma::matrix_b, 16, 16, 8, wmma::precision::tf32, wmma::col_major> bf;
            wmma::load_matrix_sync(af, hs + k0, LDH);
            wmma::load_matrix_sync(bf, ws + ntile * 16 * LDW + k0, LDW);
            wmma::mma_sync(acc, af, bf, acc);   // raw fp32 bits; HMMA.tf32 uses upper bits
        }
        wmma::store_matrix_sync(red + wid * 16 * LDR, acc, LDR, wmma::mem_row_major);
        __syncthreads();

        // ---- fused reduce + gate math + h write (256 threads: m, u) ----
        if (tid < 256) {
            const int nt = gu >> 2;
            const int nn = (gu & 3) * 4;
            float G[4];
#pragma unroll
            for (int g = 0; g < 4; ++g) {
                float sum = 0.f;
#pragma unroll
                for (int p = 0; p < 4; ++p)
                    sum += red[(p * 4 + nt) * 16 * LDR + gm * LDR + nn + g];
                G[g] = sum;
            }
            const float gi = G[0] + xgi;
            const float gf = G[1] + xgf2;
            const float gg = G[2] + xgg;
            const float go = G[3] + xgo;
            const float cn = sigmoidf_(gf) * cst[tid] + sigmoidf_(gi) * tanhf(gg);
            cst[tid] = cn;
            g_ENC[((size_t)gm*1024 + tcur)*1024 + dir*512 + grp*16 + gu] = sigmoidf_(go) * tanhf(cn);
        }

        // ---- prefetch xg for next step (overlaps barrier wait) ----
        if (s + 1 < 1024 && tid < 256) {
            const int tnext = dir ? (tcur - 1) : (tcur + 1);
            const size_t xb = ((size_t)gm * 1024 + tnext) * 2048 + grp * 16 + gu;
            xgi  = xg[xb          ];
            xgf2 = xg[xb +  512];
            xgg  = xg[xb + 1024];
            xgo  = xg[xb + 1536];
        }
        __syncthreads();

        // ---- release/acquire monotonic barrier (per-direction) ----
        if (tid == 0) {
            asm volatile("red.release.gpu.global.add.u32 [%0], 1;" :: "l"(cnt) : "memory");
            const unsigned tgt = (unsigned)(s + 1) * 32u;
            unsigned v;
            do {
                asm volatile("ld.acquire.gpu.global.b32 %0, [%1];" : "=r"(v) : "l"(cnt));
            } while (v < tgt);
        }
        __syncthreads();
    }
}

// ---------------- span mean pooling ----------------
__global__ __launch_bounds__(256) void pool_kernel(
    const int* __restrict__ heads, const int* __restrict__ tails)
{
    const int bs = blockIdx.x;
    const int b = bs >> 5;
    int lo = heads[bs] + 1, hi = tails[bs];
    if (lo < 0) lo = 0;
    if (hi > 1024) hi = 1024;
    int cnt = hi - lo; if (cnt < 1) cnt = 1;
    const float inv = 1.f / (float)cnt;
    const int h0 = threadIdx.x * 4;
    float ax = 0.f, ay = 0.f, az = 0.f, aw = 0.f;
    for (int t = lo; t < hi; ++t) {
        const float4 v = *(const float4*)(g_ENC + ((size_t)b*1024 + t)*1024 + h0);
        ax += v.x; ay += v.y; az += v.z; aw += v.w;
    }
    float4 o; o.x = ax*inv; o.y = ay*inv; o.z = az*inv; o.w = aw*inv;
    *(float4*)(g_FEATP + (size_t)bs*1024 + h0) = o;
}

// ---------------- row LayerNorm (optional residual) ----------------
__global__ __launch_bounds__(256) void ln_kernel(
    const float* __restrict__ X, const float* __restrict__ R,
    const float* __restrict__ gam, const float* __restrict__ bet,
    float* __restrict__ Y)
{
    const int r = blockIdx.x;
    const int tid = threadIdx.x;
    const size_t off = (size_t)r * 1024 + tid * 4;
    float4 v = *(const float4*)(X + off);
    if (R) {
        const float4 rv = *(const float4*)(R + off);
        v.x += rv.x; v.y += rv.y; v.z += rv.z; v.w += rv.w;
    }
    float s  = v.x + v.y + v.z + v.w;
    float ss = v.x*v.x + v.y*v.y + v.z*v.z + v.w*v.w;
#pragma unroll
    for (int o = 16; o; o >>= 1) {
        s  += __shfl_xor_sync(0xffffffffu, s, o);
        ss += __shfl_xor_sync(0xffffffffu, ss, o);
    }
    __shared__ float as_[8], ass_[8];
    if ((tid & 31) == 0) { as_[tid>>5] = s; ass_[tid>>5] = ss; }
    __syncthreads();
    s = 0.f; ss = 0.f;
#pragma unroll
    for (int w = 0; w < 8; ++w) { s += as_[w]; ss += ass_[w]; }
    const float mu  = s * (1.f/1024.f);
    const float var = ss * (1.f/1024.f) - mu*mu;
    const float inv = rsqrtf(var + LN_EPS);
    const int c0 = tid * 4;
    float4 o;
    o.x = (v.x-mu)*inv*gam[c0+0] + bet[c0+0];
    o.y = (v.y-mu)*inv*gam[c0+1] + bet[c0+1];
    o.z = (v.z-mu)*inv*gam[c0+2] + bet[c0+2];
    o.w = (v.w-mu)*inv*gam[c0+3] + bet[c0+3];
    *(float4*)(Y + off) = o;
}

// ---------------- span attention ----------------
__global__ __launch_bounds__(256) void attn_kernel(const int* __restrict__ amask)
{
    const int bh = blockIdx.x;
    const int b = bh >> 4, h = bh & 15;
    __shared__ float qs[2048], ksm[2048], vsm[2048], sc[32*33];
    __shared__ int ms[32];
    const int tid = threadIdx.x;
    for (int idx = tid; idx < 2048; idx += 256) {
        const int s = idx >> 6, d = idx & 63;
        const size_t off = (size_t)(b*32 + s)*1024 + h*64 + d;
        qs[idx] = g_Qm[off]; ksm[idx] = g_Km[off]; vsm[idx] = g_Vm[off];
    }
    if (tid < 32) ms[tid] = amask[b*32 + tid];
    __syncthreads();
    for (int idx = tid; idx < 1024; idx += 256) {
        const int i = idx >> 5, j = idx & 31;
        float d0 = 0.f;
#pragma unroll
        for (int k = 0; k < 64; ++k) d0 += qs[i*64+k] * ksm[j*64+k];
        sc[i*33 + j] = d0 * 0.125f;
    }
    __syncthreads();
    const int w = tid >> 5, l = tid & 31;
    for (int i = w; i < 32; i += 8) {
        const bool valid = (ms[i] != 0) && (ms[l] != 0);
        float v = valid ? sc[i*33 + l] : -3.402823466e38f;
        float mx = v;
#pragma unroll
        for (int o = 16; o; o >>= 1) mx = fmaxf(mx, __shfl_xor_sync(0xffffffffu, mx, o));
        float e = expf(v - mx);
        float sum = e;
#pragma unroll
        for (int o = 16; o; o >>= 1) sum += __shfl_xor_sync(0xffffffffu, sum, o);
        float p = e / sum;
        if (!valid) p = 0.f;
        sc[i*33 + l] = p;
    }
    __syncthreads();
    for (int idx = tid; idx < 2048; idx += 256) {
        const int s = idx >> 6, d = idx & 63;
        float a = 0.f;
#pragma unroll
        for (int j = 0; j < 32; ++j) a += sc[s*33 + j] * vsm[j*64 + d];
        g_CTX[(size_t)(b*32 + s)*1024 + h*64 + d] = a;
    }
}

// ---------------- classifier ----------------
__global__ __launch_bounds__(96) void cls_kernel(
    const float* __restrict__ wc, const float* __restrict__ bc,
    float* __restrict__ out)
{
    const int r = blockIdx.x;
    const int lbl = threadIdx.x >> 5, lane = threadIdx.x & 31;
    const float* a = g_ATT + (size_t)r * 1024 + lane * 32;
    const float* w = wc + (size_t)lbl * 1024 + lane * 32;
    float s = 0.f;
#pragma unroll
    for (int k = 0; k < 32; ++k) s += a[k] * w[k];
#pragma unroll
    for (int o = 16; o; o >>= 1) s += __shfl_xor_sync(0xffffffffu, s, o);
    if (lane == 0) out[r * 3 + lbl] = s + bc[lbl];
}

extern "C" void kernel_launch(void* const* d_in, const int* in_sizes, int n_in,
                              void* d_out, int out_size) {
    const float* hs    = (const float*)d_in[0];
    const float* wih_f = (const float*)d_in[1];
    const float* whh_f = (const float*)d_in[2];
    const float* b_f   = (const float*)d_in[3];
    const float* wih_b = (const float*)d_in[4];
    const float* whh_b = (const float*)d_in[5];
    const float* b_b   = (const float*)d_in[6];
    const float* ln_g  = (const float*)d_in[7];
    const float* ln_b  = (const float*)d_in[8];
    const float* wq = (const float*)d_in[9];  const float* bq = (const float*)d_in[10];
    const float* wk = (const float*)d_in[11]; const float* bk = (const float*)d_in[12];
    const float* wv = (const float*)d_in[13]; const float* bv = (const float*)d_in[14];
    const float* wo = (const float*)d_in[15]; const float* bo = (const float*)d_in[16];
    const float* aln_g = (const float*)d_in[17];
    const float* aln_b = (const float*)d_in[18];
    const float* wc = (const float*)d_in[19]; const float* bc = (const float*)d_in[20];
    const int* heads = (const int*)d_in[21];
    const int* tails = (const int*)d_in[22];
    const int* amask = (const int*)d_in[23];
    float* out = (float*)d_out;

    float *XGf, *XGb, *FEATP, *FEAT, *Qm, *Km, *Vm, *CTX, *TMP, *ATT;
    cudaGetSymbolAddress((void**)&XGf, g_XGf);
    cudaGetSymbolAddress((void**)&XGb, g_XGb);
    cudaGetSymbolAddress((void**)&FEATP, g_FEATP);
    cudaGetSymbolAddress((void**)&FEAT, g_FEAT);
    cudaGetSymbolAddress((void**)&Qm, g_Qm);
    cudaGetSymbolAddress((void**)&Km, g_Km);
    cudaGetSymbolAddress((void**)&Vm, g_Vm);
    cudaGetSymbolAddress((void**)&CTX, g_CTX);
    cudaGetSymbolAddress((void**)&TMP, g_TMP);
    cudaGetSymbolAddress((void**)&ATT, g_ATT);

    const int gemm_smem = 128 * LDC * sizeof(float);
    cudaFuncSetAttribute(gemm_tf32, cudaFuncAttributeMaxDynamicSharedMemorySize, gemm_smem);

    dim3 gXG(2048/128, 16384/128);
    gemm_tf32<<<gXG, 256, gemm_smem>>>(hs, wih_f, b_f, XGf, 16384, 2048, 1024);
    gemm_tf32<<<gXG, 256, gemm_smem>>>(hs, wih_b, b_b, XGb, 16384, 2048, 1024);

    bar_reset<<<1, 1>>>();
    const int lstm_smem = (64*LDW + 16*LDH + 16*16*LDR + 256) * sizeof(float);
    cudaFuncSetAttribute(lstm_rec, cudaFuncAttributeMaxDynamicSharedMemorySize, lstm_smem);
    lstm_rec<<<64, 512, lstm_smem>>>(whh_f, whh_b);

    pool_kernel<<<512, 256>>>(heads, tails);
    ln_kernel<<<512, 256>>>(FEATP, nullptr, ln_g, ln_b, FEAT);

    dim3 gP(1024/128, 512/128);
    gemm_tf32<<<gP, 256, gemm_smem>>>(FEAT, wq, bq, Qm, 512, 1024, 1024);
    gemm_tf32<<<gP, 256, gemm_smem>>>(FEAT, wk, bk, Km, 512, 1024, 1024);
    gemm_tf32<<<gP, 256, gemm_smem>>>(FEAT, wv, bv, Vm, 512, 1024, 1024);

    attn_kernel<<<256, 256>>>(amask);

    gemm_tf32<<<gP, 256, gemm_smem>>>(CTX, wo, bo, TMP, 512, 1024, 1024);
    ln_kernel<<<512, 256>>>(TMP, FEAT, aln_g, aln_b, ATT);

    cls_kernel<<<512, 96>>>(wc, bc, out);
}

// round 9
// speedup vs baseline: 1.8828x; 1.2491x over previous
#include <cuda_runtime.h>
#include <cuda_fp16.h>
#include <mma.h>
#include <math.h>
#include <cstdint>

using namespace nvcuda;

#define LN_EPS 1e-7f

__device__ float g_XGf[(size_t)16384 * 2048];
__device__ float g_XGb[(size_t)16384 * 2048];
__device__ float g_ENC[(size_t)16 * 1024 * 1024];
__device__ float g_FEATP[512 * 1024];
__device__ float g_FEAT [512 * 1024];
__device__ float g_Qm[512 * 1024];
__device__ float g_Km[512 * 1024];
__device__ float g_Vm[512 * 1024];
__device__ float g_CTX[512 * 1024];
__device__ float g_TMP[512 * 1024];
__device__ float g_ATT[512 * 1024];
__device__ unsigned g_cnt[64];

// fp16 operand staging
__device__ __half g_HS16[(size_t)16384 * 1024];
__device__ __half g_WF16[(size_t)2048 * 1024];
__device__ __half g_WB16[(size_t)2048 * 1024];
__device__ __half g_W16 [(size_t)1024 * 1024];
__device__ __half g_F16 [(size_t)512 * 1024];
__device__ __half g_C16 [(size_t)512 * 1024];

// ---------------- fp32 -> fp16 conversion (8 elems/thread) ----------------
__global__ __launch_bounds__(256) void f2h(
    const float* __restrict__ x, __half* __restrict__ y, int n)
{
    const int i = (blockIdx.x * 256 + threadIdx.x) * 8;
    if (i >= n) return;
    const float4 a = *(const float4*)(x + i);
    const float4 b = *(const float4*)(x + i + 4);
    union { __half2 h2[4]; float4 v; } u;
    u.h2[0] = __floats2half2_rn(a.x, a.y);
    u.h2[1] = __floats2half2_rn(a.z, a.w);
    u.h2[2] = __floats2half2_rn(b.x, b.y);
    u.h2[3] = __floats2half2_rn(b.z, b.w);
    *(float4*)(y + i) = u.v;
}

// =====================================================================
// fp16 tensor GEMM: C[M,N] = A[M,K] * B[N,K]^T + bias[N]
// CTA 128x128, BK=64, 256 threads, 8 warps (4m x 2n), warp tile 32x64.
// wmma m16n16k16, fp32 accum. Register double-buffered gmem loads.
// Requires M%128==0, N%128==0, K%64==0.
// =====================================================================
#define HLD 72    // smem halves per row (64 + 8 pad)
#define LDC 132

__global__ __launch_bounds__(256) void gemm_h(
    const __half* __restrict__ A, const __half* __restrict__ B,
    const float* __restrict__ bias, float* __restrict__ C,
    int M, int N, int K)
{
    extern __shared__ char smem[];
    __half* As = (__half*)smem;          // [128][HLD]
    __half* Bs = As + 128 * HLD;         // [128][HLD]
    float*  Co = (float*)smem;           // [128][LDC] aliased epilogue

    const int tid = threadIdx.x;
    const int wid = tid >> 5;
    const int brow = blockIdx.y * 128;
    const int bcol = blockIdx.x * 128;
    const int wm = (wid & 3) * 32;
    const int wn = (wid >> 2) * 64;

    wmma::fragment<wmma::accumulator, 16, 16, 16, float> acc[2][4];
#pragma unroll
    for (int i = 0; i < 2; ++i)
#pragma unroll
        for (int j = 0; j < 4; ++j) wmma::fill_fragment(acc[i][j], 0.f);

    const __half* Ag = A + (size_t)brow * K;
    const __half* Bg = B + (size_t)bcol * K;

    const int lr = tid >> 1;          // 0..127 (row)
    const int lc = (tid & 1) * 32;    // 0 / 32 (half col base)

    uint4 aR[4], bR[4];
#pragma unroll
    for (int q = 0; q < 4; ++q) {
        aR[q] = *(const uint4*)(Ag + (size_t)lr * K + lc + q * 8);
        bR[q] = *(const uint4*)(Bg + (size_t)lr * K + lc + q * 8);
    }

    for (int kt = 0; kt < K; kt += 64) {
#pragma unroll
        for (int q = 0; q < 4; ++q) {
            *(uint4*)(As + lr * HLD + lc + q * 8) = aR[q];
            *(uint4*)(Bs + lr * HLD + lc + q * 8) = bR[q];
        }
        __syncthreads();
        if (kt + 64 < K) {
#pragma unroll
            for (int q = 0; q < 4; ++q) {
                aR[q] = *(const uint4*)(Ag + (size_t)lr * K + kt + 64 + lc + q * 8);
                bR[q] = *(const uint4*)(Bg + (size_t)lr * K + kt + 64 + lc + q * 8);
            }
        }
#pragma unroll
        for (int kk = 0; kk < 64; kk += 16) {
            wmma::fragment<wmma::matrix_a, 16, 16, 16, __half, wmma::row_major> af[2];
            wmma::fragment<wmma::matrix_b, 16, 16, 16, __half, wmma::col_major> bf[4];
#pragma unroll
            for (int i = 0; i < 2; ++i)
                wmma::load_matrix_sync(af[i], As + (wm + i * 16) * HLD + kk, HLD);
#pragma unroll
            for (int j = 0; j < 4; ++j)
                wmma::load_matrix_sync(bf[j], Bs + (wn + j * 16) * HLD + kk, HLD);
#pragma unroll
            for (int i = 0; i < 2; ++i)
#pragma unroll
                for (int j = 0; j < 4; ++j)
                    wmma::mma_sync(acc[i][j], af[i], bf[j], acc[i][j]);
        }
        __syncthreads();
    }

#pragma unroll
    for (int i = 0; i < 2; ++i)
#pragma unroll
        for (int j = 0; j < 4; ++j)
            wmma::store_matrix_sync(Co + (wm + i * 16) * LDC + wn + j * 16,
                                    acc[i][j], LDC, wmma::mem_row_major);
    __syncthreads();

    for (int idx = tid; idx < 128 * 32; idx += 256) {
        const int r = idx >> 5, c4 = (idx & 31) * 4;
        float4 v = *(float4*)(Co + r * LDC + c4);
        v.x += bias[bcol + c4 + 0];
        v.y += bias[bcol + c4 + 1];
        v.z += bias[bcol + c4 + 2];
        v.w += bias[bcol + c4 + 3];
        *(float4*)(C + (size_t)(brow + r) * N + bcol + c4) = v;
    }
}

// =====================================================================
__global__ void bar_reset() { g_cnt[0] = 0; g_cnt[32] = 0; }

// =====================================================================
// Persistent bi-LSTM recurrence (wmma tf32 matvec; R6 version)
// =====================================================================
#define LDW 516
#define LDH 520
#define LDR 20

__device__ __forceinline__ float sigmoidf_(float x) { return 1.f / (1.f + expf(-x)); }

__global__ __launch_bounds__(512) void lstm_rec(
    const float* __restrict__ whh_f, const float* __restrict__ whh_b)
{
    extern __shared__ float sm[];
    float* ws  = sm;                     // [64][LDW]   c = u*4+gate
    float* hs  = ws + 64 * LDW;          // [16][LDH]
    float* red = hs + 16 * LDH;          // [16 warps][16][LDR]
    float* cst = red + 16 * 16 * LDR;    // [256]

    const int tid = threadIdx.x;
    const int wid = tid >> 5;
    const int dir = blockIdx.x & 1;
    const int grp = blockIdx.x >> 1;
    const float* whh = dir ? whh_b : whh_f;
    const float* xg  = dir ? g_XGb : g_XGf;
    unsigned* cnt = &g_cnt[dir * 32];

    for (int idx = tid; idx < 64 * 512; idx += 512) {
        int c = idx >> 9, k = idx & 511;
        int j = (c & 3) * 512 + grp * 16 + (c >> 2);
        ws[c * LDW + k] = whh[(size_t)j * 512 + k];
    }
    if (tid < 256) cst[tid] = 0.f;
    __syncthreads();

    const int ntile = wid & 3;
    const int kgrp  = wid >> 2;
    const int gm = tid >> 4, gu = tid & 15;

    float xgi, xgf2, xgg, xgo;
    {
        const int t0 = dir ? 1023 : 0;
        if (tid < 256) {
            const size_t xb = ((size_t)gm * 1024 + t0) * 2048 + grp * 16 + gu;
            xgi  = xg[xb       ];
            xgf2 = xg[xb +  512];
            xgg  = xg[xb + 1024];
            xgo  = xg[xb + 1536];
        }
    }

    for (int s = 0; s < 1024; ++s) {
        const int tcur = dir ? (1023 - s) : s;

        if (s == 0) {
            for (int idx = tid; idx < 16 * LDH; idx += 512) hs[idx] = 0.f;
        } else {
            const int tprev = dir ? (tcur + 1) : (tcur - 1);
            const int b  = tid >> 5;
            const int k0 = (tid & 31) * 16;
            const float* src = g_ENC + ((size_t)b * 1024 + tprev) * 1024 + dir * 512 + k0;
            float* dst = hs + b * LDH + k0;
#pragma unroll
            for (int j = 0; j < 16; j += 4)
                *(float4*)(dst + j) = *(const float4*)(src + j);
        }
        __syncthreads();

        wmma::fragment<wmma::accumulator, 16, 16, 8, float> acc;
        wmma::fill_fragment(acc, 0.f);
#pragma unroll 4
        for (int kt = 0; kt < 16; ++kt) {
            const int k0 = kgrp * 128 + kt * 8;
            wmma::fragment<wmma::matrix_a, 16, 16, 8, wmma::precision::tf32, wmma::row_major> af;
            wmma::fragment<wmma::matrix_b, 16, 16, 8, wmma::precision::tf32, wmma::col_major> bf;
            wmma::load_matrix_sync(af, hs + k0, LDH);
            wmma::load_matrix_sync(bf, ws + ntile * 16 * LDW + k0, LDW);
            wmma::mma_sync(acc, af, bf, acc);
        }
        wmma::store_matrix_sync(red + wid * 16 * LDR, acc, LDR, wmma::mem_row_major);
        __syncthreads();

        if (tid < 256) {
            const int nt = gu >> 2;
            const int nn = (gu & 3) * 4;
            float G[4];
#pragma unroll
            for (int g = 0; g < 4; ++g) {
                float sum = 0.f;
#pragma unroll
                for (int p = 0; p < 4; ++p)
                    sum += red[(p * 4 + nt) * 16 * LDR + gm * LDR + nn + g];
                G[g] = sum;
            }
            const float gi = G[0] + xgi;
            const float gf = G[1] + xgf2;
            const float gg = G[2] + xgg;
            const float go = G[3] + xgo;
            const float cn = sigmoidf_(gf) * cst[tid] + sigmoidf_(gi) * tanhf(gg);
            cst[tid] = cn;
            g_ENC[((size_t)gm*1024 + tcur)*1024 + dir*512 + grp*16 + gu] = sigmoidf_(go) * tanhf(cn);
        }

        if (s + 1 < 1024 && tid < 256) {
            const int tnext = dir ? (tcur - 1) : (tcur + 1);
            const size_t xb = ((size_t)gm * 1024 + tnext) * 2048 + grp * 16 + gu;
            xgi  = xg[xb       ];
            xgf2 = xg[xb +  512];
            xgg  = xg[xb + 1024];
            xgo  = xg[xb + 1536];
        }
        __syncthreads();

        if (tid == 0) {
            asm volatile("red.release.gpu.global.add.u32 [%0], 1;" :: "l"(cnt) : "memory");
            const unsigned tgt = (unsigned)(s + 1) * 32u;
            unsigned v;
            do {
                asm volatile("ld.acquire.gpu.global.b32 %0, [%1];" : "=r"(v) : "l"(cnt));
            } while (v < tgt);
        }
        __syncthreads();
    }
}

// ---------------- span mean pooling ----------------
__global__ __launch_bounds__(256) void pool_kernel(
    const int* __restrict__ heads, const int* __restrict__ tails)
{
    const int bs = blockIdx.x;
    const int b = bs >> 5;
    int lo = heads[bs] + 1, hi = tails[bs];
    if (lo < 0) lo = 0;
    if (hi > 1024) hi = 1024;
    int cnt = hi - lo; if (cnt < 1) cnt = 1;
    const float inv = 1.f / (float)cnt;
    const int h0 = threadIdx.x * 4;
    float ax = 0.f, ay = 0.f, az = 0.f, aw = 0.f;
    for (int t = lo; t < hi; ++t) {
        const float4 v = *(const float4*)(g_ENC + ((size_t)b*1024 + t)*1024 + h0);
        ax += v.x; ay += v.y; az += v.z; aw += v.w;
    }
    float4 o; o.x = ax*inv; o.y = ay*inv; o.z = az*inv; o.w = aw*inv;
    *(float4*)(g_FEATP + (size_t)bs*1024 + h0) = o;
}

// ---------------- row LayerNorm (optional residual) ----------------
__global__ __launch_bounds__(256) void ln_kernel(
    const float* __restrict__ X, const float* __restrict__ R,
    const float* __restrict__ gam, const float* __restrict__ bet,
    float* __restrict__ Y)
{
    const int r = blockIdx.x;
    const int tid = threadIdx.x;
    const size_t off = (size_t)r * 1024 + tid * 4;
    float4 v = *(const float4*)(X + off);
    if (R) {
        const float4 rv = *(const float4*)(R + off);
        v.x += rv.x; v.y += rv.y; v.z += rv.z; v.w += rv.w;
    }
    float s  = v.x + v.y + v.z + v.w;
    float ss = v.x*v.x + v.y*v.y + v.z*v.z + v.w*v.w;
#pragma unroll
    for (int o = 16; o; o >>= 1) {
        s  += __shfl_xor_sync(0xffffffffu, s, o);
        ss += __shfl_xor_sync(0xffffffffu, ss, o);
    }
    __shared__ float as_[8], ass_[8];
    if ((tid & 31) == 0) { as_[tid>>5] = s; ass_[tid>>5] = ss; }
    __syncthreads();
    s = 0.f; ss = 0.f;
#pragma unroll
    for (int w = 0; w < 8; ++w) { s += as_[w]; ss += ass_[w]; }
    const float mu  = s * (1.f/1024.f);
    const float var = ss * (1.f/1024.f) - mu*mu;
    const float inv = rsqrtf(var + LN_EPS);
    const int c0 = tid * 4;
    float4 o;
    o.x = (v.x-mu)*inv*gam[c0+0] + bet[c0+0];
    o.y = (v.y-mu)*inv*gam[c0+1] + bet[c0+1];
    o.z = (v.z-mu)*inv*gam[c0+2] + bet[c0+2];
    o.w = (v.w-mu)*inv*gam[c0+3] + bet[c0+3];
    *(float4*)(Y + off) = o;
}

// ---------------- span attention ----------------
__global__ __launch_bounds__(256) void attn_kernel(const int* __restrict__ amask)
{
    const int bh = blockIdx.x;
    const int b = bh >> 4, h = bh & 15;
    __shared__ float qs[2048], ksm[2048], vsm[2048], sc[32*33];
    __shared__ int ms[32];
    const int tid = threadIdx.x;
    for (int idx = tid; idx < 2048; idx += 256) {
        const int s = idx >> 6, d = idx & 63;
        const size_t off = (size_t)(b*32 + s)*1024 + h*64 + d;
        qs[idx] = g_Qm[off]; ksm[idx] = g_Km[off]; vsm[idx] = g_Vm[off];
    }
    if (tid < 32) ms[tid] = amask[b*32 + tid];
    __syncthreads();
    for (int idx = tid; idx < 1024; idx += 256) {
        const int i = idx >> 5, j = idx & 31;
        float d0 = 0.f;
#pragma unroll
        for (int k = 0; k < 64; ++k) d0 += qs[i*64+k] * ksm[j*64+k];
        sc[i*33 + j] = d0 * 0.125f;
    }
    __syncthreads();
    const int w = tid >> 5, l = tid & 31;
    for (int i = w; i < 32; i += 8) {
        const bool valid = (ms[i] != 0) && (ms[l] != 0);
        float v = valid ? sc[i*33 + l] : -3.402823466e38f;
        float mx = v;
#pragma unroll
        for (int o = 16; o; o >>= 1) mx = fmaxf(mx, __shfl_xor_sync(0xffffffffu, mx, o));
        float e = expf(v - mx);
        float sum = e;
#pragma unroll
        for (int o = 16; o; o >>= 1) sum += __shfl_xor_sync(0xffffffffu, sum, o);
        float p = e / sum;
        if (!valid) p = 0.f;
        sc[i*33 + l] = p;
    }
    __syncthreads();
    for (int idx = tid; idx < 2048; idx += 256) {
        const int s = idx >> 6, d = idx & 63;
        float a = 0.f;
#pragma unroll
        for (int j = 0; j < 32; ++j) a += sc[s*33 + j] * vsm[j*64 + d];
        g_CTX[(size_t)(b*32 + s)*1024 + h*64 + d] = a;
    }
}

// ---------------- classifier ----------------
__global__ __launch_bounds__(96) void cls_kernel(
    const float* __restrict__ wc, const float* __restrict__ bc,
    float* __restrict__ out)
{
    const int r = blockIdx.x;
    const int lbl = threadIdx.x >> 5, lane = threadIdx.x & 31;
    const float* a = g_ATT + (size_t)r * 1024 + lane * 32;
    const float* w = wc + (size_t)lbl * 1024 + lane * 32;
    float s = 0.f;
#pragma unroll
    for (int k = 0; k < 32; ++k) s += a[k] * w[k];
#pragma unroll
    for (int o = 16; o; o >>= 1) s += __shfl_xor_sync(0xffffffffu, s, o);
    if (lane == 0) out[r * 3 + lbl] = s + bc[lbl];
}

extern "C" void kernel_launch(void* const* d_in, const int* in_sizes, int n_in,
                              void* d_out, int out_size) {
    const float* hs    = (const float*)d_in[0];
    const float* wih_f = (const float*)d_in[1];
    const float* whh_f = (const float*)d_in[2];
    const float* b_f   = (const float*)d_in[3];
    const float* wih_b = (const float*)d_in[4];
    const float* whh_b = (const float*)d_in[5];
    const float* b_b   = (const float*)d_in[6];
    const float* ln_g  = (const float*)d_in[7];
    const float* ln_b  = (const float*)d_in[8];
    const float* wq = (const float*)d_in[9];  const float* bq = (const float*)d_in[10];
    const float* wk = (const float*)d_in[11]; const float* bk = (const float*)d_in[12];
    const float* wv = (const float*)d_in[13]; const float* bv = (const float*)d_in[14];
    const float* wo = (const float*)d_in[15]; const float* bo = (const float*)d_in[16];
    const float* aln_g = (const float*)d_in[17];
    const float* aln_b = (const float*)d_in[18];
    const float* wc = (const float*)d_in[19]; const float* bc = (const float*)d_in[20];
    const int* heads = (const int*)d_in[21];
    const int* tails = (const int*)d_in[22];
    const int* amask = (const int*)d_in[23];
    float* out = (float*)d_out;

    float *XGf, *XGb, *FEATP, *FEAT, *Qm, *Km, *Vm, *CTX, *TMP, *ATT;
    __half *HS16, *WF16, *WB16, *W16, *F16, *C16;
    cudaGetSymbolAddress((void**)&XGf, g_XGf);
    cudaGetSymbolAddress((void**)&XGb, g_XGb);
    cudaGetSymbolAddress((void**)&FEATP, g_FEATP);
    cudaGetSymbolAddress((void**)&FEAT, g_FEAT);
    cudaGetSymbolAddress((void**)&Qm, g_Qm);
    cudaGetSymbolAddress((void**)&Km, g_Km);
    cudaGetSymbolAddress((void**)&Vm, g_Vm);
    cudaGetSymbolAddress((void**)&CTX, g_CTX);
    cudaGetSymbolAddress((void**)&TMP, g_TMP);
    cudaGetSymbolAddress((void**)&ATT, g_ATT);
    cudaGetSymbolAddress((void**)&HS16, g_HS16);
    cudaGetSymbolAddress((void**)&WF16, g_WF16);
    cudaGetSymbolAddress((void**)&WB16, g_WB16);
    cudaGetSymbolAddress((void**)&W16,  g_W16);
    cudaGetSymbolAddress((void**)&F16,  g_F16);
    cudaGetSymbolAddress((void**)&C16,  g_C16);

    const int gsmem = 128 * LDC * sizeof(float);  // 67584
    cudaFuncSetAttribute(gemm_h, cudaFuncAttributeMaxDynamicSharedMemorySize, gsmem);

    // fp16 staging
    f2h<<<16777216/2048, 256>>>(hs,    HS16, 16777216);
    f2h<<<2097152/2048,  256>>>(wih_f, WF16, 2097152);
    f2h<<<2097152/2048,  256>>>(wih_b, WB16, 2097152);

    // input-gate GEMMs
    dim3 gXG(2048/128, 16384/128);
    gemm_h<<<gXG, 256, gsmem>>>(HS16, WF16, b_f, XGf, 16384, 2048, 1024);
    gemm_h<<<gXG, 256, gsmem>>>(HS16, WB16, b_b, XGb, 16384, 2048, 1024);

    bar_reset<<<1, 1>>>();
    const int lstm_smem = (64*LDW + 16*LDH + 16*16*LDR + 256) * sizeof(float);
    cudaFuncSetAttribute(lstm_rec, cudaFuncAttributeMaxDynamicSharedMemorySize, lstm_smem);
    lstm_rec<<<64, 512, lstm_smem>>>(whh_f, whh_b);

    pool_kernel<<<512, 256>>>(heads, tails);
    ln_kernel<<<512, 256>>>(FEATP, nullptr, ln_g, ln_b, FEAT);

    dim3 gP(1024/128, 512/128);
    f2h<<<524288/2048, 256>>>(FEAT, F16, 524288);
    f2h<<<1048576/2048, 256>>>(wq, W16, 1048576);
    gemm_h<<<gP, 256, gsmem>>>(F16, W16, bq, Qm, 512, 1024, 1024);
    f2h<<<1048576/2048, 256>>>(wk, W16, 1048576);
    gemm_h<<<gP, 256, gsmem>>>(F16, W16, bk, Km, 512, 1024, 1024);
    f2h<<<1048576/2048, 256>>>(wv, W16, 1048576);
    gemm_h<<<gP, 256, gsmem>>>(F16, W16, bv, Vm, 512, 1024, 1024);

    attn_kernel<<<256, 256>>>(amask);

    f2h<<<524288/2048, 256>>>(CTX, C16, 524288);
    f2h<<<1048576/2048, 256>>>(wo, W16, 1048576);
    gemm_h<<<gP, 256, gsmem>>>(C16, W16, bo, TMP, 512, 1024, 1024);
    ln_kernel<<<512, 256>>>(TMP, FEAT, aln_g, aln_b, ATT);

    cls_kernel<<<512, 96>>>(wc, bc, out);
}

// round 10
// speedup vs baseline: 3.3821x; 1.7963x over previous
#include <cuda_runtime.h>
#include <cuda_fp16.h>
#include <mma.h>
#include <math.h>
#include <cstdint>

using namespace nvcuda;

#define LN_EPS 1e-7f

__device__ float g_XGf[(size_t)16384 * 2048];
__device__ float g_XGb[(size_t)16384 * 2048];
__device__ __half g_ENC16[(size_t)16 * 1024 * 1024];
__device__ float g_FEATP[512 * 1024];
__device__ float g_FEAT [512 * 1024];
__device__ float g_Qm[512 * 1024];
__device__ float g_Km[512 * 1024];
__device__ float g_Vm[512 * 1024];
__device__ float g_CTX[512 * 1024];
__device__ float g_TMP[512 * 1024];
__device__ float g_ATT[512 * 1024];
__device__ unsigned g_cnt[64];

// fp16 operand staging for GEMMs
__device__ __half g_HS16[(size_t)16384 * 1024];
__device__ __half g_WF16[(size_t)2048 * 1024];
__device__ __half g_WB16[(size_t)2048 * 1024];
__device__ __half g_W16 [(size_t)1024 * 1024];
__device__ __half g_F16 [(size_t)512 * 1024];
__device__ __half g_C16 [(size_t)512 * 1024];

// ---------------- fp32 -> fp16 conversion ----------------
__global__ __launch_bounds__(256) void f2h(
    const float* __restrict__ x, __half* __restrict__ y, int n)
{
    const int i = (blockIdx.x * 256 + threadIdx.x) * 8;
    if (i >= n) return;
    const float4 a = *(const float4*)(x + i);
    const float4 b = *(const float4*)(x + i + 4);
    union { __half2 h2[4]; float4 v; } u;
    u.h2[0] = __floats2half2_rn(a.x, a.y);
    u.h2[1] = __floats2half2_rn(a.z, a.w);
    u.h2[2] = __floats2half2_rn(b.x, b.y);
    u.h2[3] = __floats2half2_rn(b.z, b.w);
    *(float4*)(y + i) = u.v;
}

// =====================================================================
// fp16 tensor GEMM: C[M,N] = A[M,K] * B[N,K]^T + bias[N]   (R9 version)
// =====================================================================
#define HLD 72
#define LDC 132

__global__ __launch_bounds__(256) void gemm_h(
    const __half* __restrict__ A, const __half* __restrict__ B,
    const float* __restrict__ bias, float* __restrict__ C,
    int M, int N, int K)
{
    extern __shared__ char smem[];
    __half* As = (__half*)smem;
    __half* Bs = As + 128 * HLD;
    float*  Co = (float*)smem;

    const int tid = threadIdx.x;
    const int wid = tid >> 5;
    const int brow = blockIdx.y * 128;
    const int bcol = blockIdx.x * 128;
    const int wm = (wid & 3) * 32;
    const int wn = (wid >> 2) * 64;

    wmma::fragment<wmma::accumulator, 16, 16, 16, float> acc[2][4];
#pragma unroll
    for (int i = 0; i < 2; ++i)
#pragma unroll
        for (int j = 0; j < 4; ++j) wmma::fill_fragment(acc[i][j], 0.f);

    const __half* Ag = A + (size_t)brow * K;
    const __half* Bg = B + (size_t)bcol * K;

    const int lr = tid >> 1;
    const int lc = (tid & 1) * 32;

    uint4 aR[4], bR[4];
#pragma unroll
    for (int q = 0; q < 4; ++q) {
        aR[q] = *(const uint4*)(Ag + (size_t)lr * K + lc + q * 8);
        bR[q] = *(const uint4*)(Bg + (size_t)lr * K + lc + q * 8);
    }

    for (int kt = 0; kt < K; kt += 64) {
#pragma unroll
        for (int q = 0; q < 4; ++q) {
            *(uint4*)(As + lr * HLD + lc + q * 8) = aR[q];
            *(uint4*)(Bs + lr * HLD + lc + q * 8) = bR[q];
        }
        __syncthreads();
        if (kt + 64 < K) {
#pragma unroll
            for (int q = 0; q < 4; ++q) {
                aR[q] = *(const uint4*)(Ag + (size_t)lr * K + kt + 64 + lc + q * 8);
                bR[q] = *(const uint4*)(Bg + (size_t)lr * K + kt + 64 + lc + q * 8);
            }
        }
#pragma unroll
        for (int kk = 0; kk < 64; kk += 16) {
            wmma::fragment<wmma::matrix_a, 16, 16, 16, __half, wmma::row_major> af[2];
            wmma::fragment<wmma::matrix_b, 16, 16, 16, __half, wmma::col_major> bf[4];
#pragma unroll
            for (int i = 0; i < 2; ++i)
                wmma::load_matrix_sync(af[i], As + (wm + i * 16) * HLD + kk, HLD);
#pragma unroll
            for (int j = 0; j < 4; ++j)
                wmma::load_matrix_sync(bf[j], Bs + (wn + j * 16) * HLD + kk, HLD);
#pragma unroll
            for (int i = 0; i < 2; ++i)
#pragma unroll
                for (int j = 0; j < 4; ++j)
                    wmma::mma_sync(acc[i][j], af[i], bf[j], acc[i][j]);
        }
        __syncthreads();
    }

#pragma unroll
    for (int i = 0; i < 2; ++i)
#pragma unroll
        for (int j = 0; j < 4; ++j)
            wmma::store_matrix_sync(Co + (wm + i * 16) * LDC + wn + j * 16,
                                    acc[i][j], LDC, wmma::mem_row_major);
    __syncthreads();

    for (int idx = tid; idx < 128 * 32; idx += 256) {
        const int r = idx >> 5, c4 = (idx & 31) * 4;
        float4 v = *(float4*)(Co + r * LDC + c4);
        v.x += bias[bcol + c4 + 0];
        v.y += bias[bcol + c4 + 1];
        v.z += bias[bcol + c4 + 2];
        v.w += bias[bcol + c4 + 3];
        *(float4*)(C + (size_t)(brow + r) * N + bcol + c4) = v;
    }
}

// =====================================================================
__global__ void bar_reset() { g_cnt[0] = 0; g_cnt[32] = 0; }

// =====================================================================
// Persistent bi-LSTM recurrence, fp16 matvec with REGISTER-RESIDENT
// weight fragments. 64 CTAs = 2 dirs x 32 grps (16 units, c = u*4+gate).
// 512 threads = 16 warps = 4 n-tiles x 4 k-groups. Per warp: 8 fixed
// m16n16k16 b-fragments (W slice), per step 8 ldmatrix a-loads + 8 mma.
// =====================================================================
#define LDW16 520   // stage pitch (halves)
#define LDH16 528   // hs pitch (halves)
#define LDR 20

__device__ __forceinline__ float sigmoidf_(float x) { return 1.f / (1.f + expf(-x)); }

__global__ __launch_bounds__(512, 1) void lstm_rec(
    const float* __restrict__ whh_f, const float* __restrict__ whh_b)
{
    extern __shared__ char smx[];
    __half* wstage = (__half*)smx;                          // [64][LDW16] (init only)
    __half* hs16   = (__half*)smx;                          // [16][LDH16]
    float*  red    = (float*)(smx + 16 * LDH16 * 2);        // [16][16][LDR]

    const int tid = threadIdx.x;
    const int wid = tid >> 5;
    const int dir = blockIdx.x & 1;
    const int grp = blockIdx.x >> 1;
    const float* whh = dir ? whh_b : whh_f;
    const float* xg  = dir ? g_XGb : g_XGf;
    unsigned* cnt = &g_cnt[dir * 32];

    // stage recurrent weights fp16: wstage[c][k], c=u*4+gate -> row gate*512+grp*16+u
    for (int idx = tid; idx < 64 * 512; idx += 512) {
        const int c = idx >> 9, k = idx & 511;
        const int j = (c & 3) * 512 + grp * 16 + (c >> 2);
        wstage[c * LDW16 + k] = __float2half(whh[(size_t)j * 512 + k]);
    }
    __syncthreads();

    // preload this warp's 8 b-fragments (constant across all steps)
    const int ntile = wid & 3;
    const int kgrp  = wid >> 2;
    wmma::fragment<wmma::matrix_b, 16, 16, 16, __half, wmma::col_major> bf[8];
#pragma unroll
    for (int kt = 0; kt < 8; ++kt)
        wmma::load_matrix_sync(bf[kt],
            wstage + (ntile * 16) * LDW16 + kgrp * 128 + kt * 16, LDW16);
    __syncthreads();   // all warps done with wstage; smem now reused

    const int gm = tid >> 4, gu = tid & 15;   // gate-phase (tid<256)
    float creg = 0.f;                          // cell state (thread-private)

    // prefetch xg for step 0
    float xgi, xgf2, xgg, xgo;
    {
        const int t0 = dir ? 1023 : 0;
        if (tid < 256) {
            const size_t xb = ((size_t)gm * 1024 + t0) * 2048 + grp * 16 + gu;
            xgi  = xg[xb       ];
            xgf2 = xg[xb +  512];
            xgg  = xg[xb + 1024];
            xgo  = xg[xb + 1536];
        }
    }

    for (int s = 0; s < 1024; ++s) {
        const int tcur = dir ? (1023 - s) : s;

        // ---- stage h_prev[16][512] fp16 ----
        if (s == 0) {
            for (int idx = tid; idx < 16 * LDH16 / 2; idx += 512)
                ((uint32_t*)hs16)[idx] = 0u;
        } else {
            const int tprev = dir ? (tcur + 1) : (tcur - 1);
            const int b  = tid >> 5;
            const int k0 = (tid & 31) * 16;
            const __half* src = g_ENC16 + ((size_t)b * 1024 + tprev) * 1024 + dir * 512 + k0;
            __half* dst = hs16 + b * LDH16 + k0;
            *(uint4*)(dst)     = *(const uint4*)(src);
            *(uint4*)(dst + 8) = *(const uint4*)(src + 8);
        }
        __syncthreads();

        // ---- tensor matvec: 8 a-loads + 8 mma against register bf ----
        wmma::fragment<wmma::accumulator, 16, 16, 16, float> acc;
        wmma::fill_fragment(acc, 0.f);
#pragma unroll
        for (int kt = 0; kt < 8; ++kt) {
            wmma::fragment<wmma::matrix_a, 16, 16, 16, __half, wmma::row_major> af;
            wmma::load_matrix_sync(af, hs16 + kgrp * 128 + kt * 16, LDH16);
            wmma::mma_sync(acc, af, bf[kt], acc);
        }
        wmma::store_matrix_sync(red + wid * 16 * LDR, acc, LDR, wmma::mem_row_major);
        __syncthreads();

        // ---- fused reduce + gate math + h write (256 threads: m=gm, u=gu) ----
        if (tid < 256) {
            const int nt = gu >> 2;
            const int nn = (gu & 3) * 4;
            float G[4];
#pragma unroll
            for (int g = 0; g < 4; ++g) {
                float sum = 0.f;
#pragma unroll
                for (int p = 0; p < 4; ++p)
                    sum += red[(p * 4 + nt) * 16 * LDR + gm * LDR + nn + g];
                G[g] = sum;
            }
            const float gi = G[0] + xgi;
            const float gf = G[1] + xgf2;
            const float gg = G[2] + xgg;
            const float go = G[3] + xgo;
            const float cn = sigmoidf_(gf) * creg + sigmoidf_(gi) * tanhf(gg);
            creg = cn;
            const float hv = sigmoidf_(go) * tanhf(cn);
            g_ENC16[((size_t)gm * 1024 + tcur) * 1024 + dir * 512 + grp * 16 + gu] =
                __float2half(hv);
        }

        // ---- prefetch xg for next step (overlaps barrier wait) ----
        if (s + 1 < 1024 && tid < 256) {
            const int tnext = dir ? (tcur - 1) : (tcur + 1);
            const size_t xb = ((size_t)gm * 1024 + tnext) * 2048 + grp * 16 + gu;
            xgi  = xg[xb       ];
            xgf2 = xg[xb +  512];
            xgg  = xg[xb + 1024];
            xgo  = xg[xb + 1536];
        }
        __syncthreads();

        // ---- release/acquire monotonic barrier (per-direction) ----
        if (tid == 0) {
            asm volatile("red.release.gpu.global.add.u32 [%0], 1;" :: "l"(cnt) : "memory");
            const unsigned tgt = (unsigned)(s + 1) * 32u;
            unsigned v;
            do {
                asm volatile("ld.acquire.gpu.global.b32 %0, [%1];" : "=r"(v) : "l"(cnt));
            } while (v < tgt);
        }
        __syncthreads();
    }
}

// ---------------- span mean pooling (fp16 enc -> fp32) ----------------
__global__ __launch_bounds__(256) void pool_kernel(
    const int* __restrict__ heads, const int* __restrict__ tails)
{
    const int bs = blockIdx.x;
    const int b = bs >> 5;
    int lo = heads[bs] + 1, hi = tails[bs];
    if (lo < 0) lo = 0;
    if (hi > 1024) hi = 1024;
    int cnt = hi - lo; if (cnt < 1) cnt = 1;
    const float inv = 1.f / (float)cnt;
    const int h0 = threadIdx.x * 4;
    float ax = 0.f, ay = 0.f, az = 0.f, aw = 0.f;
    for (int t = lo; t < hi; ++t) {
        const uint2 v = *(const uint2*)(g_ENC16 + ((size_t)b * 1024 + t) * 1024 + h0);
        const float2 f0 = __half22float2(*(const __half2*)&v.x);
        const float2 f1 = __half22float2(*(const __half2*)&v.y);
        ax += f0.x; ay += f0.y; az += f1.x; aw += f1.y;
    }
    float4 o; o.x = ax * inv; o.y = ay * inv; o.z = az * inv; o.w = aw * inv;
    *(float4*)(g_FEATP + (size_t)bs * 1024 + h0) = o;
}

// ---------------- row LayerNorm (optional residual) ----------------
__global__ __launch_bounds__(256) void ln_kernel(
    const float* __restrict__ X, const float* __restrict__ R,
    const float* __restrict__ gam, const float* __restrict__ bet,
    float* __restrict__ Y)
{
    const int r = blockIdx.x;
    const int tid = threadIdx.x;
    const size_t off = (size_t)r * 1024 + tid * 4;
    float4 v = *(const float4*)(X + off);
    if (R) {
        const float4 rv = *(const float4*)(R + off);
        v.x += rv.x; v.y += rv.y; v.z += rv.z; v.w += rv.w;
    }
    float s  = v.x + v.y + v.z + v.w;
    float ss = v.x*v.x + v.y*v.y + v.z*v.z + v.w*v.w;
#pragma unroll
    for (int o = 16; o; o >>= 1) {
        s  += __shfl_xor_sync(0xffffffffu, s, o);
        ss += __shfl_xor_sync(0xffffffffu, ss, o);
    }
    __shared__ float as_[8], ass_[8];
    if ((tid & 31) == 0) { as_[tid>>5] = s; ass_[tid>>5] = ss; }
    __syncthreads();
    s = 0.f; ss = 0.f;
#pragma unroll
    for (int w = 0; w < 8; ++w) { s += as_[w]; ss += ass_[w]; }
    const float mu  = s * (1.f/1024.f);
    const float var = ss * (1.f/1024.f) - mu*mu;
    const float inv = rsqrtf(var + LN_EPS);
    const int c0 = tid * 4;
    float4 o;
    o.x = (v.x-mu)*inv*gam[c0+0] + bet[c0+0];
    o.y = (v.y-mu)*inv*gam[c0+1] + bet[c0+1];
    o.z = (v.z-mu)*inv*gam[c0+2] + bet[c0+2];
    o.w = (v.w-mu)*inv*gam[c0+3] + bet[c0+3];
    *(float4*)(Y + off) = o;
}

// ---------------- span attention ----------------
__global__ __launch_bounds__(256) void attn_kernel(const int* __restrict__ amask)
{
    const int bh = blockIdx.x;
    const int b = bh >> 4, h = bh & 15;
    __shared__ float qs[2048], ksm[2048], vsm[2048], sc[32*33];
    __shared__ int ms[32];
    const int tid = threadIdx.x;
    for (int idx = tid; idx < 2048; idx += 256) {
        const int s = idx >> 6, d = idx & 63;
        const size_t off = (size_t)(b*32 + s)*1024 + h*64 + d;
        qs[idx] = g_Qm[off]; ksm[idx] = g_Km[off]; vsm[idx] = g_Vm[off];
    }
    if (tid < 32) ms[tid] = amask[b*32 + tid];
    __syncthreads();
    for (int idx = tid; idx < 1024; idx += 256) {
        const int i = idx >> 5, j = idx & 31;
        float d0 = 0.f;
#pragma unroll
        for (int k = 0; k < 64; ++k) d0 += qs[i*64+k] * ksm[j*64+k];
        sc[i*33 + j] = d0 * 0.125f;
    }
    __syncthreads();
    const int w = tid >> 5, l = tid & 31;
    for (int i = w; i < 32; i += 8) {
        const bool valid = (ms[i] != 0) && (ms[l] != 0);
        float v = valid ? sc[i*33 + l] : -3.402823466e38f;
        float mx = v;
#pragma unroll
        for (int o = 16; o; o >>= 1) mx = fmaxf(mx, __shfl_xor_sync(0xffffffffu, mx, o));
        float e = expf(v - mx);
        float sum = e;
#pragma unroll
        for (int o = 16; o; o >>= 1) sum += __shfl_xor_sync(0xffffffffu, sum, o);
        float p = e / sum;
        if (!valid) p = 0.f;
        sc[i*33 + l] = p;
    }
    __syncthreads();
    for (int idx = tid; idx < 2048; idx += 256) {
        const int s = idx >> 6, d = idx & 63;
        float a = 0.f;
#pragma unroll
        for (int j = 0; j < 32; ++j) a += sc[s*33 + j] * vsm[j*64 + d];
        g_CTX[(size_t)(b*32 + s)*1024 + h*64 + d] = a;
    }
}

// ---------------- classifier ----------------
__global__ __launch_bounds__(96) void cls_kernel(
    const float* __restrict__ wc, const float* __restrict__ bc,
    float* __restrict__ out)
{
    const int r = blockIdx.x;
    const int lbl = threadIdx.x >> 5, lane = threadIdx.x & 31;
    const float* a = g_ATT + (size_t)r * 1024 + lane * 32;
    const float* w = wc + (size_t)lbl * 1024 + lane * 32;
    float s = 0.f;
#pragma unroll
    for (int k = 0; k < 32; ++k) s += a[k] * w[k];
#pragma unroll
    for (int o = 16; o; o >>= 1) s += __shfl_xor_sync(0xffffffffu, s, o);
    if (lane == 0) out[r * 3 + lbl] = s + bc[lbl];
}

extern "C" void kernel_launch(void* const* d_in, const int* in_sizes, int n_in,
                              void* d_out, int out_size) {
    const float* hs    = (const float*)d_in[0];
    const float* wih_f = (const float*)d_in[1];
    const float* whh_f = (const float*)d_in[2];
    const float* b_f   = (const float*)d_in[3];
    const float* wih_b = (const float*)d_in[4];
    const float* whh_b = (const float*)d_in[5];
    const float* b_b   = (const float*)d_in[6];
    const float* ln_g  = (const float*)d_in[7];
    const float* ln_b  = (const float*)d_in[8];
    const float* wq = (const float*)d_in[9];  const float* bq = (const float*)d_in[10];
    const float* wk = (const float*)d_in[11]; const float* bk = (const float*)d_in[12];
    const float* wv = (const float*)d_in[13]; const float* bv = (const float*)d_in[14];
    const float* wo = (const float*)d_in[15]; const float* bo = (const float*)d_in[16];
    const float* aln_g = (const float*)d_in[17];
    const float* aln_b = (const float*)d_in[18];
    const float* wc = (const float*)d_in[19]; const float* bc = (const float*)d_in[20];
    const int* heads = (const int*)d_in[21];
    const int* tails = (const int*)d_in[22];
    const int* amask = (const int*)d_in[23];
    float* out = (float*)d_out;

    float *XGf, *XGb, *FEATP, *FEAT, *Qm, *Km, *Vm, *CTX, *TMP, *ATT;
    __half *HS16, *WF16, *WB16, *W16, *F16, *C16;
    cudaGetSymbolAddress((void**)&XGf, g_XGf);
    cudaGetSymbolAddress((void**)&XGb, g_XGb);
    cudaGetSymbolAddress((void**)&FEATP, g_FEATP);
    cudaGetSymbolAddress((void**)&FEAT, g_FEAT);
    cudaGetSymbolAddress((void**)&Qm, g_Qm);
    cudaGetSymbolAddress((void**)&Km, g_Km);
    cudaGetSymbolAddress((void**)&Vm, g_Vm);
    cudaGetSymbolAddress((void**)&CTX, g_CTX);
    cudaGetSymbolAddress((void**)&TMP, g_TMP);
    cudaGetSymbolAddress((void**)&ATT, g_ATT);
    cudaGetSymbolAddress((void**)&HS16, g_HS16);
    cudaGetSymbolAddress((void**)&WF16, g_WF16);
    cudaGetSymbolAddress((void**)&WB16, g_WB16);
    cudaGetSymbolAddress((void**)&W16,  g_W16);
    cudaGetSymbolAddress((void**)&F16,  g_F16);
    cudaGetSymbolAddress((void**)&C16,  g_C16);

    const int gsmem = 128 * LDC * sizeof(float);
    cudaFuncSetAttribute(gemm_h, cudaFuncAttributeMaxDynamicSharedMemorySize, gsmem);

    f2h<<<16777216/2048, 256>>>(hs,    HS16, 16777216);
    f2h<<<2097152/2048,  256>>>(wih_f, WF16, 2097152);
    f2h<<<2097152/2048,  256>>>(wih_b, WB16, 2097152);

    dim3 gXG(2048/128, 16384/128);
    gemm_h<<<gXG, 256, gsmem>>>(HS16, WF16, b_f, XGf, 16384, 2048, 1024);
    gemm_h<<<gXG, 256, gsmem>>>(HS16, WB16, b_b, XGb, 16384, 2048, 1024);

    bar_reset<<<1, 1>>>();
    const int lstm_smem = 64 * LDW16 * 2;   // 66560 B (stage; runtime fits inside)
    cudaFuncSetAttribute(lstm_rec, cudaFuncAttributeMaxDynamicSharedMemorySize, lstm_smem);
    lstm_rec<<<64, 512, lstm_smem>>>(whh_f, whh_b);

    pool_kernel<<<512, 256>>>(heads, tails);
    ln_kernel<<<512, 256>>>(FEATP, nullptr, ln_g, ln_b, FEAT);

    dim3 gP(1024/128, 512/128);
    f2h<<<524288/2048, 256>>>(FEAT, F16, 524288);
    f2h<<<1048576/2048, 256>>>(wq, W16, 1048576);
    gemm_h<<<gP, 256, gsmem>>>(F16, W16, bq, Qm, 512, 1024, 1024);
    f2h<<<1048576/2048, 256>>>(wk, W16, 1048576);
    gemm_h<<<gP, 256, gsmem>>>(F16, W16, bk, Km, 512, 1024, 1024);
    f2h<<<1048576/2048, 256>>>(wv, W16, 1048576);
    gemm_h<<<gP, 256, gsmem>>>(F16, W16, bv, Vm, 512, 1024, 1024);

    attn_kernel<<<256, 256>>>(amask);

    f2h<<<524288/2048, 256>>>(CTX, C16, 524288);
    f2h<<<1048576/2048, 256>>>(wo, W16, 1048576);
    gemm_h<<<gP, 256, gsmem>>>(C16, W16, bo, TMP, 512, 1024, 1024);
    ln_kernel<<<512, 256>>>(TMP, FEAT, aln_g, aln_b, ATT);

    cls_kernel<<<512, 96>>>(wc, bc, out);
}

// round 11
// speedup vs baseline: 3.5680x; 1.0550x over previous
#include <cuda_runtime.h>
#include <cuda_fp16.h>
#include <mma.h>
#include <math.h>
#include <cstdint>

using namespace nvcuda;

#define LN_EPS 1e-7f

__device__ float g_XGf[(size_t)16384 * 2048];
__device__ float g_XGb[(size_t)16384 * 2048];
__device__ __half g_ENC16[(size_t)16 * 1024 * 1024];
__device__ float g_FEATP[512 * 1024];
__device__ float g_FEAT [512 * 1024];
__device__ float g_Qm[512 * 1024];
__device__ float g_Km[512 * 1024];
__device__ float g_Vm[512 * 1024];
__device__ float g_CTX[512 * 1024];
__device__ float g_TMP[512 * 1024];
__device__ float g_ATT[512 * 1024];
__device__ unsigned g_cnt[64];

// fp16 operand staging
__device__ __half g_HS16[(size_t)16384 * 1024];
__device__ __half g_WF16[(size_t)2048 * 1024];
__device__ __half g_WB16[(size_t)2048 * 1024];
__device__ __half g_WQ16[(size_t)1024 * 1024];
__device__ __half g_WK16[(size_t)1024 * 1024];
__device__ __half g_WV16[(size_t)1024 * 1024];
__device__ __half g_WO16[(size_t)1024 * 1024];
__device__ __half g_F16 [(size_t)512 * 1024];
__device__ __half g_C16 [(size_t)512 * 1024];

// ---------------- fp32 -> fp16 conversion ----------------
__global__ __launch_bounds__(256) void f2h(
    const float* __restrict__ x, __half* __restrict__ y, int n)
{
    const int i = (blockIdx.x * 256 + threadIdx.x) * 8;
    if (i >= n) return;
    const float4 a = *(const float4*)(x + i);
    const float4 b = *(const float4*)(x + i + 4);
    union { __half2 h2[4]; float4 v; } u;
    u.h2[0] = __floats2half2_rn(a.x, a.y);
    u.h2[1] = __floats2half2_rn(a.z, a.w);
    u.h2[2] = __floats2half2_rn(b.x, b.y);
    u.h2[3] = __floats2half2_rn(b.z, b.w);
    *(float4*)(y + i) = u.v;
}

// =====================================================================
// fp16 tensor GEMM: C[M,N] = A[M,K] * B[N,K]^T + bias[N]
// CTA 128x128, BK=64, 256 threads, cp.async double-buffered staging,
// __launch_bounds__(256,2) -> 2 CTAs/SM. Requires M,N%128==0, K%64==0.
// smem: As0@0 Bs0@18432 As1@36864 Bs1@55296 (73728 B); Co aliases base.
// =====================================================================
#define HLD 72
#define LDC 132
#define STG_A0 0
#define STG_B0 18432
#define STG_A1 36864
#define STG_B1 55296

__global__ __launch_bounds__(256, 2) void gemm_h(
    const __half* __restrict__ A, const __half* __restrict__ B,
    const float* __restrict__ bias, float* __restrict__ C,
    int M, int N, int K)
{
    extern __shared__ char smem[];
    float* Co = (float*)smem;

    const int tid = threadIdx.x;
    const int wid = tid >> 5;
    const int brow = blockIdx.y * 128;
    const int bcol = blockIdx.x * 128;
    const int wm = (wid & 3) * 32;
    const int wn = (wid >> 2) * 64;

    const __half* Ag = A + (size_t)brow * K;
    const __half* Bg = B + (size_t)bcol * K;

    wmma::fragment<wmma::accumulator, 16, 16, 16, float> acc[2][4];
#pragma unroll
    for (int i = 0; i < 2; ++i)
#pragma unroll
        for (int j = 0; j < 4; ++j) wmma::fill_fragment(acc[i][j], 0.f);

    // chunk map: idx = tid + p*256 -> row = idx>>3, col = (idx&7)*8 halves (16B)
    auto issue_stage = [&](int aoff, int boff, int kt) {
#pragma unroll
        for (int p = 0; p < 4; ++p) {
            const int idx = tid + p * 256;
            const int r = idx >> 3, c = (idx & 7) * 8;
            const unsigned da = (unsigned)__cvta_generic_to_shared(
                smem + aoff + (r * HLD + c) * 2);
            const unsigned db = (unsigned)__cvta_generic_to_shared(
                smem + boff + (r * HLD + c) * 2);
            asm volatile("cp.async.cg.shared.global [%0], [%1], 16;"
                         :: "r"(da), "l"(Ag + (size_t)r * K + kt + c));
            asm volatile("cp.async.cg.shared.global [%0], [%1], 16;"
                         :: "r"(db), "l"(Bg + (size_t)r * K + kt + c));
        }
    };

    issue_stage(STG_A0, STG_B0, 0);
    asm volatile("cp.async.commit_group;");

    int buf = 0;
    for (int kt = 0; kt < K; kt += 64) {
        if (kt + 64 < K)
            issue_stage(buf ? STG_A0 : STG_A1, buf ? STG_B0 : STG_B1, kt + 64);
        asm volatile("cp.async.commit_group;");
        asm volatile("cp.async.wait_group 1;");
        __syncthreads();

        const __half* As = (const __half*)(smem + (buf ? STG_A1 : STG_A0));
        const __half* Bs = (const __half*)(smem + (buf ? STG_B1 : STG_B0));
#pragma unroll
        for (int kk = 0; kk < 64; kk += 16) {
            wmma::fragment<wmma::matrix_a, 16, 16, 16, __half, wmma::row_major> af[2];
            wmma::fragment<wmma::matrix_b, 16, 16, 16, __half, wmma::col_major> bf[4];
#pragma unroll
            for (int i = 0; i < 2; ++i)
                wmma::load_matrix_sync(af[i], As + (wm + i * 16) * HLD + kk, HLD);
#pragma unroll
            for (int j = 0; j < 4; ++j)
                wmma::load_matrix_sync(bf[j], Bs + (wn + j * 16) * HLD + kk, HLD);
#pragma unroll
            for (int i = 0; i < 2; ++i)
#pragma unroll
                for (int j = 0; j < 4; ++j)
                    wmma::mma_sync(acc[i][j], af[i], bf[j], acc[i][j]);
        }
        __syncthreads();
        buf ^= 1;
    }

#pragma unroll
    for (int i = 0; i < 2; ++i)
#pragma unroll
        for (int j = 0; j < 4; ++j)
            wmma::store_matrix_sync(Co + (wm + i * 16) * LDC + wn + j * 16,
                                    acc[i][j], LDC, wmma::mem_row_major);
    __syncthreads();

    for (int idx = tid; idx < 128 * 32; idx += 256) {
        const int r = idx >> 5, c4 = (idx & 31) * 4;
        float4 v = *(float4*)(Co + r * LDC + c4);
        v.x += bias[bcol + c4 + 0];
        v.y += bias[bcol + c4 + 1];
        v.z += bias[bcol + c4 + 2];
        v.w += bias[bcol + c4 + 3];
        *(float4*)(C + (size_t)(brow + r) * N + bcol + c4) = v;
    }
}

// =====================================================================
__global__ void bar_reset() { g_cnt[0] = 0; g_cnt[32] = 0; }

// =====================================================================
// Persistent bi-LSTM recurrence (R10 version: register-resident W frags)
// =====================================================================
#define LDW16 520
#define LDH16 528
#define LDR 20

__device__ __forceinline__ float sigmoidf_(float x) { return 1.f / (1.f + expf(-x)); }

__global__ __launch_bounds__(512, 1) void lstm_rec(
    const float* __restrict__ whh_f, const float* __restrict__ whh_b)
{
    extern __shared__ char smx[];
    __half* wstage = (__half*)smx;
    __half* hs16   = (__half*)smx;
    float*  red    = (float*)(smx + 16 * LDH16 * 2);

    const int tid = threadIdx.x;
    const int wid = tid >> 5;
    const int dir = blockIdx.x & 1;
    const int grp = blockIdx.x >> 1;
    const float* whh = dir ? whh_b : whh_f;
    const float* xg  = dir ? g_XGb : g_XGf;
    unsigned* cnt = &g_cnt[dir * 32];

    for (int idx = tid; idx < 64 * 512; idx += 512) {
        const int c = idx >> 9, k = idx & 511;
        const int j = (c & 3) * 512 + grp * 16 + (c >> 2);
        wstage[c * LDW16 + k] = __float2half(whh[(size_t)j * 512 + k]);
    }
    __syncthreads();

    const int ntile = wid & 3;
    const int kgrp  = wid >> 2;
    wmma::fragment<wmma::matrix_b, 16, 16, 16, __half, wmma::col_major> bf[8];
#pragma unroll
    for (int kt = 0; kt < 8; ++kt)
        wmma::load_matrix_sync(bf[kt],
            wstage + (ntile * 16) * LDW16 + kgrp * 128 + kt * 16, LDW16);
    __syncthreads();

    const int gm = tid >> 4, gu = tid & 15;
    float creg = 0.f;

    float xgi, xgf2, xgg, xgo;
    {
        const int t0 = dir ? 1023 : 0;
        if (tid < 256) {
            const size_t xb = ((size_t)gm * 1024 + t0) * 2048 + grp * 16 + gu;
            xgi  = xg[xb       ];
            xgf2 = xg[xb +  512];
            xgg  = xg[xb + 1024];
            xgo  = xg[xb + 1536];
        }
    }

    for (int s = 0; s < 1024; ++s) {
        const int tcur = dir ? (1023 - s) : s;

        if (s == 0) {
            for (int idx = tid; idx < 16 * LDH16 / 2; idx += 512)
                ((uint32_t*)hs16)[idx] = 0u;
        } else {
            const int tprev = dir ? (tcur + 1) : (tcur - 1);
            const int b  = tid >> 5;
            const int k0 = (tid & 31) * 16;
            const __half* src = g_ENC16 + ((size_t)b * 1024 + tprev) * 1024 + dir * 512 + k0;
            __half* dst = hs16 + b * LDH16 + k0;
            *(uint4*)(dst)     = *(const uint4*)(src);
            *(uint4*)(dst + 8) = *(const uint4*)(src + 8);
        }
        __syncthreads();

        wmma::fragment<wmma::accumulator, 16, 16, 16, float> acc;
        wmma::fill_fragment(acc, 0.f);
#pragma unroll
        for (int kt = 0; kt < 8; ++kt) {
            wmma::fragment<wmma::matrix_a, 16, 16, 16, __half, wmma::row_major> af;
            wmma::load_matrix_sync(af, hs16 + kgrp * 128 + kt * 16, LDH16);
            wmma::mma_sync(acc, af, bf[kt], acc);
        }
        wmma::store_matrix_sync(red + wid * 16 * LDR, acc, LDR, wmma::mem_row_major);
        __syncthreads();

        if (tid < 256) {
            const int nt = gu >> 2;
            const int nn = (gu & 3) * 4;
            float G[4];
#pragma unroll
            for (int g = 0; g < 4; ++g) {
                float sum = 0.f;
#pragma unroll
                for (int p = 0; p < 4; ++p)
                    sum += red[(p * 4 + nt) * 16 * LDR + gm * LDR + nn + g];
                G[g] = sum;
            }
            const float gi = G[0] + xgi;
            const float gf = G[1] + xgf2;
            const float gg = G[2] + xgg;
            const float go = G[3] + xgo;
            const float cn = sigmoidf_(gf) * creg + sigmoidf_(gi) * tanhf(gg);
            creg = cn;
            const float hv = sigmoidf_(go) * tanhf(cn);
            g_ENC16[((size_t)gm * 1024 + tcur) * 1024 + dir * 512 + grp * 16 + gu] =
                __float2half(hv);
        }

        if (s + 1 < 1024 && tid < 256) {
            const int tnext = dir ? (tcur - 1) : (tcur + 1);
            const size_t xb = ((size_t)gm * 1024 + tnext) * 2048 + grp * 16 + gu;
            xgi  = xg[xb       ];
            xgf2 = xg[xb +  512];
            xgg  = xg[xb + 1024];
            xgo  = xg[xb + 1536];
        }
        __syncthreads();

        if (tid == 0) {
            asm volatile("red.release.gpu.global.add.u32 [%0], 1;" :: "l"(cnt) : "memory");
            const unsigned tgt = (unsigned)(s + 1) * 32u;
            unsigned v;
            do {
                asm volatile("ld.acquire.gpu.global.b32 %0, [%1];" : "=r"(v) : "l"(cnt));
            } while (v < tgt);
        }
        __syncthreads();
    }
}

// ---------------- span mean pooling ----------------
__global__ __launch_bounds__(256) void pool_kernel(
    const int* __restrict__ heads, const int* __restrict__ tails)
{
    const int bs = blockIdx.x;
    const int b = bs >> 5;
    int lo = heads[bs] + 1, hi = tails[bs];
    if (lo < 0) lo = 0;
    if (hi > 1024) hi = 1024;
    int cnt = hi - lo; if (cnt < 1) cnt = 1;
    const float inv = 1.f / (float)cnt;
    const int h0 = threadIdx.x * 4;
    float ax = 0.f, ay = 0.f, az = 0.f, aw = 0.f;
    for (int t = lo; t < hi; ++t) {
        const uint2 v = *(const uint2*)(g_ENC16 + ((size_t)b * 1024 + t) * 1024 + h0);
        const float2 f0 = __half22float2(*(const __half2*)&v.x);
        const float2 f1 = __half22float2(*(const __half2*)&v.y);
        ax += f0.x; ay += f0.y; az += f1.x; aw += f1.y;
    }
    float4 o; o.x = ax * inv; o.y = ay * inv; o.z = az * inv; o.w = aw * inv;
    *(float4*)(g_FEATP + (size_t)bs * 1024 + h0) = o;
}

// ---------------- row LayerNorm ----------------
__global__ __launch_bounds__(256) void ln_kernel(
    const float* __restrict__ X, const float* __restrict__ R,
    const float* __restrict__ gam, const float* __restrict__ bet,
    float* __restrict__ Y)
{
    const int r = blockIdx.x;
    const int tid = threadIdx.x;
    const size_t off = (size_t)r * 1024 + tid * 4;
    float4 v = *(const float4*)(X + off);
    if (R) {
        const float4 rv = *(const float4*)(R + off);
        v.x += rv.x; v.y += rv.y; v.z += rv.z; v.w += rv.w;
    }
    float s  = v.x + v.y + v.z + v.w;
    float ss = v.x*v.x + v.y*v.y + v.z*v.z + v.w*v.w;
#pragma unroll
    for (int o = 16; o; o >>= 1) {
        s  += __shfl_xor_sync(0xffffffffu, s, o);
        ss += __shfl_xor_sync(0xffffffffu, ss, o);
    }
    __shared__ float as_[8], ass_[8];
    if ((tid & 31) == 0) { as_[tid>>5] = s; ass_[tid>>5] = ss; }
    __syncthreads();
    s = 0.f; ss = 0.f;
#pragma unroll
    for (int w = 0; w < 8; ++w) { s += as_[w]; ss += ass_[w]; }
    const float mu  = s * (1.f/1024.f);
    const float var = ss * (1.f/1024.f) - mu*mu;
    const float inv = rsqrtf(var + LN_EPS);
    const int c0 = tid * 4;
    float4 o;
    o.x = (v.x-mu)*inv*gam[c0+0] + bet[c0+0];
    o.y = (v.y-mu)*inv*gam[c0+1] + bet[c0+1];
    o.z = (v.z-mu)*inv*gam[c0+2] + bet[c0+2];
    o.w = (v.w-mu)*inv*gam[c0+3] + bet[c0+3];
    *(float4*)(Y + off) = o;
}

// ---------------- span attention ----------------
__global__ __launch_bounds__(256) void attn_kernel(const int* __restrict__ amask)
{
    const int bh = blockIdx.x;
    const int b = bh >> 4, h = bh & 15;
    __shared__ float qs[2048], ksm[2048], vsm[2048], sc[32*33];
    __shared__ int ms[32];
    const int tid = threadIdx.x;
    for (int idx = tid; idx < 2048; idx += 256) {
        const int s = idx >> 6, d = idx & 63;
        const size_t off = (size_t)(b*32 + s)*1024 + h*64 + d;
        qs[idx] = g_Qm[off]; ksm[idx] = g_Km[off]; vsm[idx] = g_Vm[off];
    }
    if (tid < 32) ms[tid] = amask[b*32 + tid];
    __syncthreads();
    for (int idx = tid; idx < 1024; idx += 256) {
        const int i = idx >> 5, j = idx & 31;
        float d0 = 0.f;
#pragma unroll
        for (int k = 0; k < 64; ++k) d0 += qs[i*64+k] * ksm[j*64+k];
        sc[i*33 + j] = d0 * 0.125f;
    }
    __syncthreads();
    const int w = tid >> 5, l = tid & 31;
    for (int i = w; i < 32; i += 8) {
        const bool valid = (ms[i] != 0) && (ms[l] != 0);
        float v = valid ? sc[i*33 + l] : -3.402823466e38f;
        float mx = v;
#pragma unroll
        for (int o = 16; o; o >>= 1) mx = fmaxf(mx, __shfl_xor_sync(0xffffffffu, mx, o));
        float e = expf(v - mx);
        float sum = e;
#pragma unroll
        for (int o = 16; o; o >>= 1) sum += __shfl_xor_sync(0xffffffffu, sum, o);
        float p = e / sum;
        if (!valid) p = 0.f;
        sc[i*33 + l] = p;
    }
    __syncthreads();
    for (int idx = tid; idx < 2048; idx += 256) {
        const int s = idx >> 6, d = idx & 63;
        float a = 0.f;
#pragma unroll
        for (int j = 0; j < 32; ++j) a += sc[s*33 + j] * vsm[j*64 + d];
        g_CTX[(size_t)(b*32 + s)*1024 + h*64 + d] = a;
    }
}

// ---------------- classifier ----------------
__global__ __launch_bounds__(96) void cls_kernel(
    const float* __restrict__ wc, const float* __restrict__ bc,
    float* __restrict__ out)
{
    const int r = blockIdx.x;
    const int lbl = threadIdx.x >> 5, lane = threadIdx.x & 31;
    const float* a = g_ATT + (size_t)r * 1024 + lane * 32;
    const float* w = wc + (size_t)lbl * 1024 + lane * 32;
    float s = 0.f;
#pragma unroll
    for (int k = 0; k < 32; ++k) s += a[k] * w[k];
#pragma unroll
    for (int o = 16; o; o >>= 1) s += __shfl_xor_sync(0xffffffffu, s, o);
    if (lane == 0) out[r * 3 + lbl] = s + bc[lbl];
}

extern "C" void kernel_launch(void* const* d_in, const int* in_sizes, int n_in,
                              void* d_out, int out_size) {
    const float* hs    = (const float*)d_in[0];
    const float* wih_f = (const float*)d_in[1];
    const float* whh_f = (const float*)d_in[2];
    const float* b_f   = (const float*)d_in[3];
    const float* wih_b = (const float*)d_in[4];
    const float* whh_b = (const float*)d_in[5];
    const float* b_b   = (const float*)d_in[6];
    const float* ln_g  = (const float*)d_in[7];
    const float* ln_b  = (const float*)d_in[8];
    const float* wq = (const float*)d_in[9];  const float* bq = (const float*)d_in[10];
    const float* wk = (const float*)d_in[11]; const float* bk = (const float*)d_in[12];
    const float* wv = (const float*)d_in[13]; const float* bv = (const float*)d_in[14];
    const float* wo = (const float*)d_in[15]; const float* bo = (const float*)d_in[16];
    const float* aln_g = (const float*)d_in[17];
    const float* aln_b = (const float*)d_in[18];
    const float* wc = (const float*)d_in[19]; const float* bc = (const float*)d_in[20];
    const int* heads = (const int*)d_in[21];
    const int* tails = (const int*)d_in[22];
    const int* amask = (const int*)d_in[23];
    float* out = (float*)d_out;

    float *XGf, *XGb, *FEATP, *FEAT, *Qm, *Km, *Vm, *CTX, *TMP, *ATT;
    __half *HS16, *WF16, *WB16, *WQ16, *WK16, *WV16, *WO16, *F16, *C16;
    cudaGetSymbolAddress((void**)&XGf, g_XGf);
    cudaGetSymbolAddress((void**)&XGb, g_XGb);
    cudaGetSymbolAddress((void**)&FEATP, g_FEATP);
    cudaGetSymbolAddress((void**)&FEAT, g_FEAT);
    cudaGetSymbolAddress((void**)&Qm, g_Qm);
    cudaGetSymbolAddress((void**)&Km, g_Km);
    cudaGetSymbolAddress((void**)&Vm, g_Vm);
    cudaGetSymbolAddress((void**)&CTX, g_CTX);
    cudaGetSymbolAddress((void**)&TMP, g_TMP);
    cudaGetSymbolAddress((void**)&ATT, g_ATT);
    cudaGetSymbolAddress((void**)&HS16, g_HS16);
    cudaGetSymbolAddress((void**)&WF16, g_WF16);
    cudaGetSymbolAddress((void**)&WB16, g_WB16);
    cudaGetSymbolAddress((void**)&WQ16, g_WQ16);
    cudaGetSymbolAddress((void**)&WK16, g_WK16);
    cudaGetSymbolAddress((void**)&WV16, g_WV16);
    cudaGetSymbolAddress((void**)&WO16, g_WO16);
    cudaGetSymbolAddress((void**)&F16,  g_F16);
    cudaGetSymbolAddress((void**)&C16,  g_C16);

    const int gsmem = 73728;
    cudaFuncSetAttribute(gemm_h, cudaFuncAttributeMaxDynamicSharedMemorySize, gsmem);

    // all weight conversions up front (overlap with XG GEMMs downstream)
    f2h<<<16777216/2048, 256>>>(hs,    HS16, 16777216);
    f2h<<<2097152/2048,  256>>>(wih_f, WF16, 2097152);
    f2h<<<2097152/2048,  256>>>(wih_b, WB16, 2097152);
    f2h<<<1048576/2048,  256>>>(wq, WQ16, 1048576);
    f2h<<<1048576/2048,  256>>>(wk, WK16, 1048576);
    f2h<<<1048576/2048,  256>>>(wv, WV16, 1048576);
    f2h<<<1048576/2048,  256>>>(wo, WO16, 1048576);

    dim3 gXG(2048/128, 16384/128);
    gemm_h<<<gXG, 256, gsmem>>>(HS16, WF16, b_f, XGf, 16384, 2048, 1024);
    gemm_h<<<gXG, 256, gsmem>>>(HS16, WB16, b_b, XGb, 16384, 2048, 1024);

    bar_reset<<<1, 1>>>();
    const int lstm_smem = 64 * LDW16 * 2;
    cudaFuncSetAttribute(lstm_rec, cudaFuncAttributeMaxDynamicSharedMemorySize, lstm_smem);
    lstm_rec<<<64, 512, lstm_smem>>>(whh_f, whh_b);

    pool_kernel<<<512, 256>>>(heads, tails);
    ln_kernel<<<512, 256>>>(FEATP, nullptr, ln_g, ln_b, FEAT);

    dim3 gP(1024/128, 512/128);
    f2h<<<524288/2048, 256>>>(FEAT, F16, 524288);
    gemm_h<<<gP, 256, gsmem>>>(F16, WQ16, bq, Qm, 512, 1024, 1024);
    gemm_h<<<gP, 256, gsmem>>>(F16, WK16, bk, Km, 512, 1024, 1024);
    gemm_h<<<gP, 256, gsmem>>>(F16, WV16, bv, Vm, 512, 1024, 1024);

    attn_kernel<<<256, 256>>>(amask);

    f2h<<<524288/2048, 256>>>(CTX, C16, 524288);
    gemm_h<<<gP, 256, gsmem>>>(C16, WO16, bo, TMP, 512, 1024, 1024);
    ln_kernel<<<512, 256>>>(TMP, FEAT, aln_g, aln_b, ATT);

    cls_kernel<<<512, 96>>>(wc, bc, out);
}